// round 15
// baseline (speedup 1.0000x reference)
#include <cuda_runtime.h>
#include <cuda_bf16.h>
#include <math.h>

#define GRIDD 128
#define GRID3 (GRIDD*GRIDD*GRIDD)
#define NB 4
#define CH 128
#define KP 32
#define MAXN 100352
#define SA 136   // smem row stride in bf16

static __device__ int    d_grid[NB*GRID3];
static __device__ int2   d_pairs[27*MAXN];
static __device__ int    d_cnt[27];
static __device__ float  d_x[MAXN*CH];
static __device__ float  d_sum[CH];
static __device__ float  d_sumsq[CH];
static __device__ float  d_bna[CH];
static __device__ float  d_bnb[CH];
static __device__ unsigned d_bnctr;
static __device__ float  d_pz[NB*KP];
static __device__ float  d_ctx[NB*KP*CH];
static __device__ float  d_kh[NB*KP*CH];
static __device__ float  d_vh[NB*KP*CH];
static __device__ float  d_WT[3*CH*CH];
static __device__ float  d_b2[CH];
static __device__ __nv_bfloat16 d_Wb[3*2*CH*CH];    // 0=Wc, 1=Wq, 2=W2fold; {hi,lo} [co][ci]
static __device__ __nv_bfloat16 d_Wcs[26*2*CH*CH];  // 26 off-center conv weights, {hi,lo} [co][ci]

__device__ __forceinline__ unsigned smem_u32(const void* p){
    unsigned a;
    asm("{ .reg .u64 t; cvta.to.shared.u64 t, %1; cvt.u32.u64 %0, t; }" : "=r"(a) : "l"(p));
    return a;
}
__device__ __forceinline__ void ldsm4(unsigned* r, unsigned addr){
    asm volatile("ldmatrix.sync.aligned.m8n8.x4.shared.b16 {%0,%1,%2,%3}, [%4];"
        : "=r"(r[0]), "=r"(r[1]), "=r"(r[2]), "=r"(r[3]) : "r"(addr));
}
__device__ __forceinline__ void mma16816(float* d, const unsigned* a, const unsigned* b){
    asm volatile("mma.sync.aligned.m16n8k16.row.col.f32.bf16.bf16.f32 "
        "{%0,%1,%2,%3}, {%4,%5,%6,%7}, {%8,%9}, {%0,%1,%2,%3};"
        : "+f"(d[0]), "+f"(d[1]), "+f"(d[2]), "+f"(d[3])
        : "r"(a[0]), "r"(a[1]), "r"(a[2]), "r"(a[3]), "r"(b[0]), "r"(b[1]));
}
__device__ __forceinline__ void split_store(__nv_bfloat16* hi, __nv_bfloat16* lo,
                                            int base, float4 v){
    __nv_bfloat16 hx=__float2bfloat16_rn(v.x), hy=__float2bfloat16_rn(v.y);
    __nv_bfloat16 hz=__float2bfloat16_rn(v.z), hw=__float2bfloat16_rn(v.w);
    __nv_bfloat162 h01; h01.x=hx; h01.y=hy;
    __nv_bfloat162 h23; h23.x=hz; h23.y=hw;
    *(__nv_bfloat162*)(hi + base)     = h01;
    *(__nv_bfloat162*)(hi + base + 2) = h23;
    __nv_bfloat162 l01, l23;
    l01.x = __float2bfloat16_rn(v.x - __bfloat162float(hx));
    l01.y = __float2bfloat16_rn(v.y - __bfloat162float(hy));
    l23.x = __float2bfloat16_rn(v.z - __bfloat162float(hz));
    l23.y = __float2bfloat16_rn(v.w - __bfloat162float(hw));
    *(__nv_bfloat162*)(lo + base)     = l01;
    *(__nv_bfloat162*)(lo + base + 2) = l23;
}
__device__ __forceinline__ void split2(float a, __nv_bfloat16* hi, __nv_bfloat16* lo, int idx){
    __nv_bfloat16 h = __float2bfloat16_rn(a);
    hi[idx] = h;
    lo[idx] = __float2bfloat16_rn(a - __bfloat162float(h));
}

// 128-row HMMA mainloop (8 warps, warp tile 64x32). acc[4][4][4] filled; no epilogue.
__device__ __forceinline__ void mma_main_128(
    unsigned sb_ah, unsigned sb_al, unsigned sb_wh, unsigned sb_wl,
    int wid, int lane, float acc[4][4][4])
{
    int mrow = (wid & 1)*64, ncol = (wid >> 1)*32;
    #pragma unroll
    for (int mi = 0; mi < 4; mi++)
        #pragma unroll
        for (int ni = 0; ni < 4; ni++)
            #pragma unroll
            for (int j = 0; j < 4; j++) acc[mi][ni][j] = 0.f;

    int arow = mrow + (lane & 15);
    int akoff = (lane >> 4)*8;
    int bi = lane >> 3;
    int brow = ncol + ((bi >> 1)*8) + (lane & 7);
    int bkoff = (bi & 1)*8;
    unsigned aAh = sb_ah + (arow*SA + akoff)*2;
    unsigned aAl = sb_al + (arow*SA + akoff)*2;
    unsigned aWh = sb_wh + (brow*SA + bkoff)*2;
    unsigned aWl = sb_wl + (brow*SA + bkoff)*2;

    #pragma unroll
    for (int kk = 0; kk < 8; kk++){
        unsigned kb = kk*32;
        unsigned ah[4][4], al[4][4], bh[4][2], bl[4][2];
        #pragma unroll
        for (int mi = 0; mi < 4; mi++){
            ldsm4(ah[mi], aAh + mi*(16*SA*2) + kb);
            ldsm4(al[mi], aAl + mi*(16*SA*2) + kb);
        }
        {
            unsigned t0[4], t1[4];
            ldsm4(t0, aWh + kb);
            ldsm4(t1, aWh + 16*SA*2 + kb);
            bh[0][0]=t0[0]; bh[0][1]=t0[1]; bh[1][0]=t0[2]; bh[1][1]=t0[3];
            bh[2][0]=t1[0]; bh[2][1]=t1[1]; bh[3][0]=t1[2]; bh[3][1]=t1[3];
            ldsm4(t0, aWl + kb);
            ldsm4(t1, aWl + 16*SA*2 + kb);
            bl[0][0]=t0[0]; bl[0][1]=t0[1]; bl[1][0]=t0[2]; bl[1][1]=t0[3];
            bl[2][0]=t1[0]; bl[2][1]=t1[1]; bl[3][0]=t1[2]; bl[3][1]=t1[3];
        }
        #pragma unroll
        for (int mi = 0; mi < 4; mi++)
            #pragma unroll
            for (int ni = 0; ni < 4; ni++){
                mma16816(acc[mi][ni], ah[mi], bh[ni]);
                mma16816(acc[mi][ni], al[mi], bh[ni]);
                mma16816(acc[mi][ni], ah[mi], bl[ni]);
            }
    }
}

// ---------------- fused prep: weights + clears + Wcs tile-transpose + d_x zero ----------------
__global__ void k_prep(const float* __restrict__ ipw, const float* __restrict__ conv_w,
                       const float* __restrict__ bw, const float* __restrict__ wop,
                       const float* __restrict__ bop, int N){
    __shared__ float we[CH];
    __shared__ float tile[CH][17];
    int bx = blockIdx.x, tid = threadIdx.x;
    if (bx < 128){
        if (tid < CH) we[tid] = bw[bx*256 + tid] + bw[bx*256 + 128 + tid];
        __syncthreads();
        if (tid < CH){
            float a = 0.f;
            #pragma unroll 8
            for (int t = 0; t < CH; t++) a += we[t]*wop[t*CH + tid];
            split2(a, d_Wb + 4*CH*CH, d_Wb + 5*CH*CH, bx*CH + tid);
            if (tid == 0){
                float s = 0.f;
                for (int t = 0; t < CH; t++) s += we[t]*bop[t];
                d_b2[bx] = s;
            }
        }
    } else if (bx < 192){
        int i0 = (bx - 128)*256 + tid;
        split2(ipw[i0], d_Wb + 2*CH*CH, d_Wb + 3*CH*CH, i0);
        {
            int o = i0 >> 7, c = i0 & 127;
            split2(conv_w[13*CH*CH + c*CH + o], d_Wb, d_Wb + CH*CH, i0);
        }
        {
            int ci = i0 >> 7, co = i0 & 127;
            d_WT[CH*CH   + i0] = ipw[(CH   + co)*CH + ci];
            d_WT[2*CH*CH + i0] = ipw[(2*CH + co)*CH + ci];
        }
    } else if (bx == 192){
        for (int i = tid; i < NB*KP*CH; i += 256) d_ctx[i] = 0.f;
        if (tid < CH){ d_sum[tid]=0.f; d_sumsq[tid]=0.f; }
        if (tid < NB*KP) d_pz[tid]=0.f;
        if (tid < 27) d_cnt[tid]=0;
    } else if (bx < 401){
        // Wcs transpose+split via smem tile: 26 offsets x 8 co-chunks of 16
        int idx = bx - 193;
        int y = idx >> 3, c0 = (idx & 7)*16;
        int kidx = y + (y >= 13);
        const float* W = conv_w + kidx*CH*CH;
        __nv_bfloat16* hi = d_Wcs + y*2*CH*CH;
        __nv_bfloat16* lo = hi + CH*CH;
        for (int i = tid; i < CH*16; i += 256){
            int ci = i >> 4, cc = i & 15;
            tile[ci][cc] = W[ci*CH + c0 + cc];   // coalesced-ish row segments
        }
        __syncthreads();
        for (int i = tid; i < 16*CH; i += 256){
            int cc = i >> 7, ci = i & 127;
            split2(tile[ci][cc], hi, lo, (c0 + cc)*CH + ci);   // coalesced writes
        }
    } else {
        int i = (bx - 401)*256 + tid;
        if (i < N*CH/4) ((float4*)d_x)[i] = make_float4(0.f,0.f,0.f,0.f);
    }
}

// ---------------- rulebook ----------------
__global__ void k_build_grid(const int* __restrict__ coords, int N){
    int n = blockIdx.x*blockDim.x + threadIdx.x;
    if (n >= N) return;
    int b = coords[4*n], x = coords[4*n+1], y = coords[4*n+2], z = coords[4*n+3];
    d_grid[b*GRID3 + (x<<14) + (y<<7) + z] = n + 1;
}
__global__ void k_build_pairs(const int* __restrict__ coords, int N){
    int n = blockIdx.x*blockDim.x + threadIdx.x;
    bool valid = n < N;
    int nn = valid ? n : N - 1;
    int b = coords[4*nn], x = coords[4*nn+1], y = coords[4*nn+2], z = coords[4*nn+3];
    const int* gb = d_grid + b*GRID3;
    int lane = threadIdx.x & 31;
    unsigned lmlt = (1u << lane) - 1u;
    int kidx = 0;
    #pragma unroll
    for (int dx = -1; dx <= 1; dx++)
    #pragma unroll
    for (int dy = -1; dy <= 1; dy++)
    #pragma unroll
    for (int dz = -1; dz <= 1; dz++){
        if (kidx != 13){
            int nx = x+dx, ny = y+dy, nz = z+dz;
            bool ok = false; int j = 0;
            if (valid && nx>=0 && nx<GRIDD && ny>=0 && ny<GRIDD && nz>=0 && nz<GRIDD){
                j = gb[(nx<<14) + (ny<<7) + nz];
                ok = j > 0;
            }
            unsigned mask = __ballot_sync(0xffffffffu, ok);
            if (ok){
                int leader = __ffs(mask) - 1;
                int pos0 = 0;
                if (lane == leader) pos0 = atomicAdd(&d_cnt[kidx], __popc(mask));
                pos0 = __shfl_sync(mask, pos0, leader);
                int pos = pos0 + __popc(mask & lmlt);
                d_pairs[kidx*MAXN + pos] = make_int2(n, j-1);
            }
        }
        kidx++;
    }
}

// ================ fused dense-center + sparse-offset conv (HMMA, atomic scatter) ================
// blocks [0, gGemm): dense center GEMM, persistent over 64-row tiles
// blocks [gGemm, gGemm+208): sparse offsets, y=idx>>3, x-stride 8
#define G64_SMEM (384*SA*2)   // 104448 bytes

__global__ void __launch_bounds__(256, 2)
k_gemm_conv(const float* __restrict__ A, int N, int gGemm){
    extern __shared__ __nv_bfloat16 smb[];
    unsigned sb = smem_u32(smb);
    int bx = blockIdx.x;
    int tid = threadIdx.x;
    int wid = tid >> 5, lane = tid & 31;

    bool isconv = bx >= gGemm;
    int kidx = 13, pbase = 0, cnt = N, tstart = bx, stride = gGemm;
    const __nv_bfloat16* Wsrc = d_Wb;
    if (isconv){
        int idx = bx - gGemm;
        int y = idx >> 3;
        kidx = y + (y >= 13);
        pbase = kidx*MAXN;
        cnt = d_cnt[kidx];
        tstart = idx & 7;
        stride = 8;
        Wsrc = d_Wcs + y*2*CH*CH;
    }
    int ntile = (cnt + 63) >> 6;
    if (tstart >= ntile) return;

    // stage split W
    {
        const int4* src = (const int4*)Wsrc;
        #pragma unroll
        for (int i = tid; i < 4096; i += 256){
            int sel = i >> 11, rem = i & 2047;
            int r = rem >> 4, c8 = rem & 15;
            __nv_bfloat16* dst = smb + (sel ? 256*SA : 128*SA) + r*SA + c8*8;
            *(int4*)dst = src[i];
        }
    }

    int mrow = (wid & 1)*32, ncol = (wid >> 1)*32;
    int arow = mrow + (lane & 15);
    int akoff = (lane >> 4)*8;
    int bi = lane >> 3;
    int brow = ncol + ((bi >> 1)*8) + (lane & 7);
    int bkoff = (bi & 1)*8;
    unsigned aAh = sb + (arow*SA + akoff)*2;
    unsigned aAl = sb + (64*SA + arow*SA + akoff)*2;
    unsigned aWh = sb + (128*SA + brow*SA + bkoff)*2;
    unsigned aWl = sb + (256*SA + brow*SA + bkoff)*2;

    int gr = tid >> 2, gc0 = (tid & 3)*32;

    for (int t = tstart; t < ntile; t += stride){
        int p0 = t << 6;
        int m = min(64, cnt - p0);
        __syncthreads();   // previous tile consumed
        {
            int src = -1;
            if (gr < m) src = isconv ? d_pairs[pbase + p0 + gr].y : (p0 + gr);
            #pragma unroll
            for (int cc = 0; cc < 32; cc += 4){
                int c = gc0 + cc;
                float4 v = make_float4(0.f,0.f,0.f,0.f);
                if (src >= 0) v = *(const float4*)&A[src*CH + c];
                split_store(smb, smb + 64*SA, gr*SA + c, v);
            }
        }
        __syncthreads();

        float acc[2][4][4];
        #pragma unroll
        for (int mi = 0; mi < 2; mi++)
            #pragma unroll
            for (int ni = 0; ni < 4; ni++)
                #pragma unroll
                for (int j = 0; j < 4; j++) acc[mi][ni][j] = 0.f;

        #pragma unroll
        for (int kk = 0; kk < 8; kk++){
            unsigned kb = kk*32;
            unsigned ah[2][4], al[2][4], bh[4][2], bl[4][2];
            #pragma unroll
            for (int mi = 0; mi < 2; mi++){
                ldsm4(ah[mi], aAh + mi*(16*SA*2) + kb);
                ldsm4(al[mi], aAl + mi*(16*SA*2) + kb);
            }
            {
                unsigned t0[4], t1[4];
                ldsm4(t0, aWh + kb);
                ldsm4(t1, aWh + 16*SA*2 + kb);
                bh[0][0]=t0[0]; bh[0][1]=t0[1]; bh[1][0]=t0[2]; bh[1][1]=t0[3];
                bh[2][0]=t1[0]; bh[2][1]=t1[1]; bh[3][0]=t1[2]; bh[3][1]=t1[3];
                ldsm4(t0, aWl + kb);
                ldsm4(t1, aWl + 16*SA*2 + kb);
                bl[0][0]=t0[0]; bl[0][1]=t0[1]; bl[1][0]=t0[2]; bl[1][1]=t0[3];
                bl[2][0]=t1[0]; bl[2][1]=t1[1]; bl[3][0]=t1[2]; bl[3][1]=t1[3];
            }
            #pragma unroll
            for (int mi = 0; mi < 2; mi++)
                #pragma unroll
                for (int ni = 0; ni < 4; ni++){
                    mma16816(acc[mi][ni], ah[mi], bh[ni]);
                    mma16816(acc[mi][ni], al[mi], bh[ni]);
                    mma16816(acc[mi][ni], ah[mi], bl[ni]);
                }
        }

        // atomic scatter epilogue
        int rb = mrow + (lane >> 2);
        int cb = ncol + 2*(lane & 3);
        int px[4];
        #pragma unroll
        for (int r4 = 0; r4 < 4; r4++){
            int row = rb + r4*8;
            px[r4] = (row < m) ? (isconv ? d_pairs[pbase + p0 + row].x : (p0 + row)) : -1;
        }
        #pragma unroll
        for (int ni = 0; ni < 4; ni++){
            int col = cb + ni*8;
            #pragma unroll
            for (int mi = 0; mi < 2; mi++){
                int p1 = px[mi*2], p2 = px[mi*2 + 1];
                if (p1 >= 0){
                    atomicAdd(&d_x[p1*CH + col],     acc[mi][ni][0]);
                    atomicAdd(&d_x[p1*CH + col + 1], acc[mi][ni][1]);
                }
                if (p2 >= 0){
                    atomicAdd(&d_x[p2*CH + col],     acc[mi][ni][2]);
                    atomicAdd(&d_x[p2*CH + col + 1], acc[mi][ni][3]);
                }
            }
        }
    }
}

// ---------------- merged mid: BN stats+finalize, psum, unset_grid ----------------
__global__ void k_mid(const float* __restrict__ gamma, const float* __restrict__ beta,
                      const float* __restrict__ probs, const int* __restrict__ coords,
                      int N, int nbbn, int npz){
    int bx = blockIdx.x, tid = threadIdx.x;
    if (bx < nbbn){
        int c = tid & 127, half = tid >> 7;
        int r0 = bx*256 + half*128;
        int lim = min(128, N - r0);
        float s = 0.f, q = 0.f;
        for (int r = 0; r < lim; r++){
            float v = d_x[(r0+r)*CH + c];
            s += v; q += v*v;
        }
        atomicAdd(&d_sum[c], s);
        atomicAdd(&d_sumsq[c], q);
        __shared__ unsigned lastv;
        __syncthreads();
        if (tid == 0){
            __threadfence();
            lastv = atomicAdd(&d_bnctr, 1u);
        }
        __syncthreads();
        if (lastv == (unsigned)(nbbn - 1)){
            if (tid < CH){
                float inv = 1.f/(float)N;
                float mu = d_sum[tid]*inv;
                float var = d_sumsq[tid]*inv - mu*mu;
                float a = gamma[tid]*rsqrtf(var + 1e-5f);
                d_bna[tid] = a;
                d_bnb[tid] = beta[tid] - mu*a;
            }
            if (tid == 0) d_bnctr = 0;
        }
    } else if (bx < nbbn + npz){
        int n0 = (bx - nbbn)*1000;
        int npb = N / NB;
        int b = n0 / npb;
        int k = tid & 31, slot = tid >> 5;
        float z = 0.f;
        for (int i = slot; i < 1000; i += 8)
            z += __expf(probs[(n0+i)*KP + k]);
        __shared__ float sr[8][KP];
        sr[slot][k] = z;
        __syncthreads();
        if (tid < KP){
            float zz = sr[0][tid];
            #pragma unroll
            for (int s2 = 1; s2 < 8; s2++) zz += sr[s2][tid];
            atomicAdd(&d_pz[b*KP + tid], zz);
        }
    } else {
        int n = (bx - nbbn - npz)*256 + tid;
        if (n < N){
            int b = coords[4*n], x = coords[4*n+1], y = coords[4*n+2], z = coords[4*n+3];
            d_grid[b*GRID3 + (x<<14) + (y<<7) + z] = 0;
        }
    }
}

// ---------------- ctx: 10-point rounds ----------------
__global__ void __launch_bounds__(256)
k_ctx(const int* __restrict__ coords, const float* __restrict__ probs, int N){
    __shared__ float wsh[2][10][KP];
    __shared__ float szs[KP];
    int n0 = blockIdx.x*200;
    if (n0 >= N) return;
    int b = coords[4*n0];
    int tid = threadIdx.x;
    int half = tid >> 7, t = tid & 127;
    if (tid < KP) szs[tid] = d_pz[b*KP + tid];
    float ba = d_bna[t], bb = d_bnb[t];
    __syncthreads();
    float acc[KP];
    #pragma unroll
    for (int k = 0; k < KP; k++) acc[k] = 0.f;
    int base = n0 + half*100;
    for (int g = 0; g < 100; g += 10){
        {
            int p = t >> 5, k = t & 31;
            int n = base + g + p;
            wsh[half][p][k] = (n < N) ? __expf(probs[n*KP + k]) / szs[k] : 0.f;
        }
        {
            int p = 4 + (t >> 5), k = t & 31;
            int n = base + g + p;
            wsh[half][p][k] = (n < N) ? __expf(probs[n*KP + k]) / szs[k] : 0.f;
        }
        if (t < 64){
            int p = 8 + (t >> 5), k = t & 31;
            int n = base + g + p;
            wsh[half][p][k] = (n < N) ? __expf(probs[n*KP + k]) / szs[k] : 0.f;
        }
        __syncthreads();
        #pragma unroll
        for (int p2 = 0; p2 < 10; p2++){
            int n2 = base + g + p2;
            float xv = (n2 < N) ? fmaxf(fmaf(d_x[n2*CH + t], ba, bb), 0.f) : 0.f;
            #pragma unroll
            for (int k2 = 0; k2 < KP; k2++) acc[k2] += wsh[half][p2][k2]*xv;
        }
        __syncthreads();
    }
    #pragma unroll
    for (int k2 = 0; k2 < KP; k2++)
        atomicAdd(&d_ctx[(b*KP+k2)*CH + t], acc[k2]);
}

// ---------------- K/V projections ----------------
__global__ void k_kvproj(const float* __restrict__ ipb){
    int row = blockIdx.x;
    int co = threadIdx.x;
    __shared__ float cr[CH];
    cr[co] = d_ctx[row*CH + co];
    __syncthreads();
    float ak = 0.f, av = 0.f;
    #pragma unroll 8
    for (int ci = 0; ci < CH; ci++){
        float c = cr[ci];
        ak += c*d_WT[CH*CH   + ci*CH + co];
        av += c*d_WT[2*CH*CH + ci*CH + co];
    }
    d_kh[row*CH + co] = ak + ipb[CH + co];
    d_vh[row*CH + co] = av + ipb[2*CH + co];
}

// ======== fused q-GEMM + attention + output GEMM ========
#define FQ_R1 0
#define FQ_R2 69632
#define FQ_KV 139264
#define FQ_TOT 172032

__global__ void __launch_bounds__(256, 1)
k_attn_out(const int* __restrict__ coords, const float* __restrict__ ipb,
           float* __restrict__ out, int N){
    extern __shared__ char sm[];
    unsigned sb = smem_u32(sm);
    __nv_bfloat16* r1h = (__nv_bfloat16*)(sm + FQ_R1);
    __nv_bfloat16* r1l = r1h + 128*SA;
    __nv_bfloat16* r2h = (__nv_bfloat16*)(sm + FQ_R2);
    __nv_bfloat16* r2l = r2h + 128*SA;
    float* qsm = (float*)(sm + FQ_R1);
    float* sK = (float*)(sm + FQ_KV);
    float* sV = sK + KP*CH;
    int tid = threadIdx.x;
    int wid = tid >> 5, lane = tid & 31;
    int n0 = blockIdx.x*128;
    if (n0 >= N) return;
    int b0 = coords[4*n0];
    int b1 = coords[4*min(n0 + 127, N - 1)];

    {
        int r = tid >> 1, c0 = (tid & 1)*64;
        int g = n0 + r;
        #pragma unroll
        for (int cc = 0; cc < 64; cc += 4){
            int c = c0 + cc;
            float4 v = make_float4(0.f,0.f,0.f,0.f);
            if (g < N) v = *(const float4*)&d_x[g*CH + c];
            v.x = fmaxf(fmaf(v.x, d_bna[c  ], d_bnb[c  ]), 0.f);
            v.y = fmaxf(fmaf(v.y, d_bna[c+1], d_bnb[c+1]), 0.f);
            v.z = fmaxf(fmaf(v.z, d_bna[c+2], d_bnb[c+2]), 0.f);
            v.w = fmaxf(fmaf(v.w, d_bna[c+3], d_bnb[c+3]), 0.f);
            split_store(r1h, r1l, r*SA + c, v);
        }
    }
    {
        const int4* src = (const int4*)(d_Wb + 2*CH*CH);
        #pragma unroll
        for (int i = tid; i < 4096; i += 256){
            int sel = i >> 11, rem = i & 2047;
            int r = rem >> 4, c8 = rem & 15;
            __nv_bfloat16* dst = (sel ? r2l : r2h) + r*SA + c8*8;
            *(int4*)dst = src[i];
        }
    }
    for (int i = tid; i < KP*CH/4; i += 256){
        ((float4*)sK)[i] = ((const float4*)(d_kh + b0*KP*CH))[i];
        ((float4*)sV)[i] = ((const float4*)(d_vh + b0*KP*CH))[i];
    }
    __syncthreads();

    float qacc[4][4][4];
    mma_main_128(sb + FQ_R1, sb + FQ_R1 + 128*SA*2, sb + FQ_R2, sb + FQ_R2 + 128*SA*2,
                 wid, lane, qacc);
    __syncthreads();
    {
        int mrow = (wid & 1)*64, ncol = (wid >> 1)*32;
        int rbase = mrow + (lane >> 2);
        int cbase = ncol + 2*(lane & 3);
        #pragma unroll
        for (int ni = 0; ni < 4; ni++){
            int col = cbase + ni*8;
            float b0f = ipb[col], b1f = ipb[col+1];
            #pragma unroll
            for (int mi = 0; mi < 4; mi++){
                int r0 = rbase + mi*16;
                *(float2*)&qsm[r0*132 + col] =
                    make_float2(0.25f*(qacc[mi][ni][0]+b0f), 0.25f*(qacc[mi][ni][1]+b1f));
                *(float2*)&qsm[(r0+8)*132 + col] =
                    make_float2(0.25f*(qacc[mi][ni][2]+b0f), 0.25f*(qacc[mi][ni][3]+b1f));
            }
        }
    }
    __syncthreads();

    for (int pp = 0; pp < 16; pp += 2){
        int r1 = wid*16 + pp;
        int n1 = n0 + r1, n2 = n1 + 1;
        bool one = (n1 < N), two = (n2 < N);
        int bsel = (one && coords[4*n1] != b0) ? 1 : 0;
        float4 q1 = *(const float4*)&qsm[r1*132 + 4*lane];
        float4 q2 = *(const float4*)&qsm[(r1+1)*132 + 4*lane];
        float s1[KP], s2[KP];
        #pragma unroll
        for (int k = 0; k < KP; k++){
            float4 kv = bsel ? *(const float4*)&d_kh[(b1*KP + k)*CH + 4*lane]
                             : *(const float4*)&sK[k*CH + 4*lane];
            s1[k] = q1.x*kv.x + q1.y*kv.y + q1.z*kv.z + q1.w*kv.w;
            s2[k] = q2.x*kv.x + q2.y*kv.y + q2.z*kv.z + q2.w*kv.w;
        }
        #pragma unroll
        for (int k = 0; k < KP; k++){
            s1[k] += __shfl_xor_sync(0xffffffffu, s1[k], 1);
            s1[k] += __shfl_xor_sync(0xffffffffu, s1[k], 2);
            s2[k] += __shfl_xor_sync(0xffffffffu, s2[k], 1);
            s2[k] += __shfl_xor_sync(0xffffffffu, s2[k], 2);
        }
        float m1 = -3.4e38f, m2 = -3.4e38f;
        #pragma unroll
        for (int k = 0; k < KP; k++){ m1 = fmaxf(m1, s1[k]); m2 = fmaxf(m2, s2[k]); }
        float z1 = 0.f, z2 = 0.f;
        #pragma unroll
        for (int k = 0; k < KP; k++){
            s1[k] = __expf(s1[k] - m1); z1 += s1[k];
            s2[k] = __expf(s2[k] - m2); z2 += s2[k];
        }
        float i1 = 1.f/z1, i2 = 1.f/z2;
        float4 o1 = make_float4(0,0,0,0), o2 = make_float4(0,0,0,0);
        #pragma unroll
        for (int k = 0; k < KP; k++){
            float4 vvv = bsel ? *(const float4*)&d_vh[(b1*KP + k)*CH + 4*lane]
                              : *(const float4*)&sV[k*CH + 4*lane];
            o1.x += s1[k]*vvv.x; o1.y += s1[k]*vvv.y; o1.z += s1[k]*vvv.z; o1.w += s1[k]*vvv.w;
            o2.x += s2[k]*vvv.x; o2.y += s2[k]*vvv.y; o2.z += s2[k]*vvv.z; o2.w += s2[k]*vvv.w;
        }
        if (!one){ o1 = make_float4(0,0,0,0); i1 = 0.f; }
        if (!two){ o2 = make_float4(0,0,0,0); i2 = 0.f; }
        o1.x*=i1; o1.y*=i1; o1.z*=i1; o1.w*=i1;
        o2.x*=i2; o2.y*=i2; o2.z*=i2; o2.w*=i2;
        split_store(r2h, r2l, r1*SA + 4*lane, o1);
        split_store(r2h, r2l, (r1+1)*SA + 4*lane, o2);
    }
    __syncthreads();

    {
        const int4* src = (const int4*)(d_Wb + 4*CH*CH);
        #pragma unroll
        for (int i = tid; i < 4096; i += 256){
            int sel = i >> 11, rem = i & 2047;
            int r = rem >> 4, c8 = rem & 15;
            __nv_bfloat16* dst = (sel ? r1l : r1h) + r*SA + c8*8;
            *(int4*)dst = src[i];
        }
    }
    __syncthreads();
    float acc[4][4][4];
    mma_main_128(sb + FQ_R2, sb + FQ_R2 + 128*SA*2, sb + FQ_R1, sb + FQ_R1 + 128*SA*2,
                 wid, lane, acc);
    {
        int mrow = (wid & 1)*64, ncol = (wid >> 1)*32;
        int rbase = n0 + mrow + (lane >> 2);
        int cbase = ncol + 2*(lane & 3);
        #pragma unroll
        for (int ni = 0; ni < 4; ni++){
            int col = cbase + ni*8;
            float b0f = d_b2[col], b1f = d_b2[col+1];
            #pragma unroll
            for (int mi = 0; mi < 4; mi++){
                int g0 = rbase + mi*16;
                if (g0 < N)
                    *(float2*)&out[g0*CH + col] =
                        make_float2(acc[mi][ni][0]+b0f, acc[mi][ni][1]+b1f);
                if (g0 + 8 < N)
                    *(float2*)&out[(g0+8)*CH + col] =
                        make_float2(acc[mi][ni][2]+b0f, acc[mi][ni][3]+b1f);
            }
        }
    }
}

extern "C" void kernel_launch(void* const* d_in, const int* in_sizes, int n_in,
                              void* d_out, int out_size){
    const float* feats  = (const float*)d_in[0];
    const float* probs  = (const float*)d_in[1];
    const float* conv_w = (const float*)d_in[2];
    const float* gamma  = (const float*)d_in[3];
    const float* beta   = (const float*)d_in[4];
    const float* ipw    = (const float*)d_in[5];
    const float* ipb    = (const float*)d_in[6];
    const float* opw    = (const float*)d_in[7];
    const float* opb    = (const float*)d_in[8];
    const float* bw     = (const float*)d_in[9];
    const int*   coords = (const int*)d_in[10];
    float* out = (float*)d_out;
    int N = in_sizes[0] / CH;

    static bool init = false;
    if (!init){
        init = true;
        cudaFuncSetAttribute(k_gemm_conv, cudaFuncAttributeMaxDynamicSharedMemorySize, G64_SMEM);
        cudaFuncSetAttribute(k_attn_out,  cudaFuncAttributeMaxDynamicSharedMemorySize, FQ_TOT);
    }
    int nb256 = (N + 255)/256;
    int nbA = (N + 127)/128;
    int ntile = (N + 63)/64;
    int gG = min(296, ntile);
    int npz = N/1000;
    int nbz = (N*CH/4 + 255)/256;

    k_prep<<<401 + nbz, 256>>>(ipw, conv_w, bw, opw, opb, N);
    k_build_grid<<<nb256, 256>>>(coords, N);
    k_build_pairs<<<nb256, 256>>>(coords, N);
    k_gemm_conv<<<gG + 208, 256, G64_SMEM>>>(feats, N, gG);
    k_mid<<<nb256 + npz + nb256, 256>>>(gamma, beta, probs, coords, N, nb256, npz);
    k_ctx<<<(N+199)/200, 256>>>(coords, probs, N);
    k_kvproj<<<NB*KP, 128>>>(ipb);
    k_attn_out<<<nbA, 256, FQ_TOT>>>(coords, ipb, out, N);
}

// round 16
// speedup vs baseline: 1.4467x; 1.4467x over previous
#include <cuda_runtime.h>
#include <cuda_bf16.h>
#include <math.h>

#define GRIDD 128
#define GRID3 (GRIDD*GRIDD*GRIDD)
#define NB 4
#define CH 128
#define KP 32
#define MAXN 100352
#define SA 136   // smem row stride in bf16

static __device__ int    d_grid[NB*GRID3];
static __device__ int2   d_pairs[27*MAXN];
static __device__ int    d_cnt[27];
static __device__ float  d_x[MAXN*CH];
static __device__ float  d_sum[CH];
static __device__ float  d_sumsq[CH];
static __device__ float  d_bna[CH];
static __device__ float  d_bnb[CH];
static __device__ unsigned d_bnctr;
static __device__ float  d_pz[NB*KP];
static __device__ float  d_ctx[NB*KP*CH];
static __device__ float  d_kh[NB*KP*CH];
static __device__ float  d_vh[NB*KP*CH];
static __device__ float  d_WT[3*CH*CH];
static __device__ float  d_b2[CH];
static __device__ __nv_bfloat16 d_Wb[3*2*CH*CH];    // 0=Wc, 1=Wq, 2=W2fold; {hi,lo} [co][ci]
static __device__ __nv_bfloat16 d_Wcs[26*2*CH*CH];  // 26 off-center conv weights, {hi,lo} [co][ci]

__device__ __forceinline__ unsigned smem_u32(const void* p){
    unsigned a;
    asm("{ .reg .u64 t; cvta.to.shared.u64 t, %1; cvt.u32.u64 %0, t; }" : "=r"(a) : "l"(p));
    return a;
}
__device__ __forceinline__ void ldsm4(unsigned* r, unsigned addr){
    asm volatile("ldmatrix.sync.aligned.m8n8.x4.shared.b16 {%0,%1,%2,%3}, [%4];"
        : "=r"(r[0]), "=r"(r[1]), "=r"(r[2]), "=r"(r[3]) : "r"(addr));
}
__device__ __forceinline__ void mma16816(float* d, const unsigned* a, const unsigned* b){
    asm volatile("mma.sync.aligned.m16n8k16.row.col.f32.bf16.bf16.f32 "
        "{%0,%1,%2,%3}, {%4,%5,%6,%7}, {%8,%9}, {%0,%1,%2,%3};"
        : "+f"(d[0]), "+f"(d[1]), "+f"(d[2]), "+f"(d[3])
        : "r"(a[0]), "r"(a[1]), "r"(a[2]), "r"(a[3]), "r"(b[0]), "r"(b[1]));
}
__device__ __forceinline__ void split_store(__nv_bfloat16* hi, __nv_bfloat16* lo,
                                            int base, float4 v){
    __nv_bfloat16 hx=__float2bfloat16_rn(v.x), hy=__float2bfloat16_rn(v.y);
    __nv_bfloat16 hz=__float2bfloat16_rn(v.z), hw=__float2bfloat16_rn(v.w);
    __nv_bfloat162 h01; h01.x=hx; h01.y=hy;
    __nv_bfloat162 h23; h23.x=hz; h23.y=hw;
    *(__nv_bfloat162*)(hi + base)     = h01;
    *(__nv_bfloat162*)(hi + base + 2) = h23;
    __nv_bfloat162 l01, l23;
    l01.x = __float2bfloat16_rn(v.x - __bfloat162float(hx));
    l01.y = __float2bfloat16_rn(v.y - __bfloat162float(hy));
    l23.x = __float2bfloat16_rn(v.z - __bfloat162float(hz));
    l23.y = __float2bfloat16_rn(v.w - __bfloat162float(hw));
    *(__nv_bfloat162*)(lo + base)     = l01;
    *(__nv_bfloat162*)(lo + base + 2) = l23;
}
__device__ __forceinline__ void split2(float a, __nv_bfloat16* hi, __nv_bfloat16* lo, int idx){
    __nv_bfloat16 h = __float2bfloat16_rn(a);
    hi[idx] = h;
    lo[idx] = __float2bfloat16_rn(a - __bfloat162float(h));
}

// 128-row HMMA mainloop (8 warps, warp tile 64x32). acc[4][4][4] filled; no epilogue.
__device__ __forceinline__ void mma_main_128(
    unsigned sb_ah, unsigned sb_al, unsigned sb_wh, unsigned sb_wl,
    int wid, int lane, float acc[4][4][4])
{
    int mrow = (wid & 1)*64, ncol = (wid >> 1)*32;
    #pragma unroll
    for (int mi = 0; mi < 4; mi++)
        #pragma unroll
        for (int ni = 0; ni < 4; ni++)
            #pragma unroll
            for (int j = 0; j < 4; j++) acc[mi][ni][j] = 0.f;

    int arow = mrow + (lane & 15);
    int akoff = (lane >> 4)*8;
    int bi = lane >> 3;
    int brow = ncol + ((bi >> 1)*8) + (lane & 7);
    int bkoff = (bi & 1)*8;
    unsigned aAh = sb_ah + (arow*SA + akoff)*2;
    unsigned aAl = sb_al + (arow*SA + akoff)*2;
    unsigned aWh = sb_wh + (brow*SA + bkoff)*2;
    unsigned aWl = sb_wl + (brow*SA + bkoff)*2;

    #pragma unroll
    for (int kk = 0; kk < 8; kk++){
        unsigned kb = kk*32;
        unsigned ah[4][4], al[4][4], bh[4][2], bl[4][2];
        #pragma unroll
        for (int mi = 0; mi < 4; mi++){
            ldsm4(ah[mi], aAh + mi*(16*SA*2) + kb);
            ldsm4(al[mi], aAl + mi*(16*SA*2) + kb);
        }
        {
            unsigned t0[4], t1[4];
            ldsm4(t0, aWh + kb);
            ldsm4(t1, aWh + 16*SA*2 + kb);
            bh[0][0]=t0[0]; bh[0][1]=t0[1]; bh[1][0]=t0[2]; bh[1][1]=t0[3];
            bh[2][0]=t1[0]; bh[2][1]=t1[1]; bh[3][0]=t1[2]; bh[3][1]=t1[3];
            ldsm4(t0, aWl + kb);
            ldsm4(t1, aWl + 16*SA*2 + kb);
            bl[0][0]=t0[0]; bl[0][1]=t0[1]; bl[1][0]=t0[2]; bl[1][1]=t0[3];
            bl[2][0]=t1[0]; bl[2][1]=t1[1]; bl[3][0]=t1[2]; bl[3][1]=t1[3];
        }
        #pragma unroll
        for (int mi = 0; mi < 4; mi++)
            #pragma unroll
            for (int ni = 0; ni < 4; ni++){
                mma16816(acc[mi][ni], ah[mi], bh[ni]);
                mma16816(acc[mi][ni], al[mi], bh[ni]);
                mma16816(acc[mi][ni], ah[mi], bl[ni]);
            }
    }
}

// ---------------- fused prep (+ coalesced conv weight transpose-splits) ----------------
__global__ void k_prep(const float* __restrict__ ipw, const float* __restrict__ conv_w,
                       const float* __restrict__ bw, const float* __restrict__ wop,
                       const float* __restrict__ bop){
    __shared__ float we[CH];
    __shared__ float tile[CH][17];
    int bx = blockIdx.x, tid = threadIdx.x;
    if (bx < 128){
        if (tid < CH) we[tid] = bw[bx*256 + tid] + bw[bx*256 + 128 + tid];
        __syncthreads();
        if (tid < CH){
            float a = 0.f;
            #pragma unroll 8
            for (int t = 0; t < CH; t++) a += we[t]*wop[t*CH + tid];
            split2(a, d_Wb + 4*CH*CH, d_Wb + 5*CH*CH, bx*CH + tid);
            if (tid == 0){
                float s = 0.f;
                for (int t = 0; t < CH; t++) s += we[t]*bop[t];
                d_b2[bx] = s;
            }
        }
    } else if (bx < 192){
        int i0 = (bx - 128)*256 + tid;
        split2(ipw[i0], d_Wb + 2*CH*CH, d_Wb + 3*CH*CH, i0);
        {
            int o = i0 >> 7, c = i0 & 127;
            split2(conv_w[13*CH*CH + c*CH + o], d_Wb, d_Wb + CH*CH, i0);
        }
        {
            int ci = i0 >> 7, co = i0 & 127;
            d_WT[CH*CH   + i0] = ipw[(CH   + co)*CH + ci];
            d_WT[2*CH*CH + i0] = ipw[(2*CH + co)*CH + ci];
        }
    } else if (bx == 192){
        for (int i = tid; i < NB*KP*CH; i += 256) d_ctx[i] = 0.f;
        if (tid < CH){ d_sum[tid]=0.f; d_sumsq[tid]=0.f; }
        if (tid < NB*KP) d_pz[tid]=0.f;
        if (tid < 27) d_cnt[tid]=0;
    } else {
        // coalesced Wcs transpose+split via smem tile: 26 offsets x 8 co-chunks of 16
        int idx = bx - 193;
        int y = idx >> 3, c0 = (idx & 7)*16;
        int kidx = y + (y >= 13);
        const float* W = conv_w + kidx*CH*CH;
        __nv_bfloat16* hi = d_Wcs + y*2*CH*CH;
        __nv_bfloat16* lo = hi + CH*CH;
        for (int i = tid; i < CH*16; i += 256){
            int ci = i >> 4, cc = i & 15;
            tile[ci][cc] = W[ci*CH + c0 + cc];
        }
        __syncthreads();
        for (int i = tid; i < 16*CH; i += 256){
            int cc = i >> 7, ci = i & 127;
            split2(tile[ci][cc], hi, lo, (c0 + cc)*CH + ci);
        }
    }
}

// ---------------- rulebook ----------------
__global__ void k_build_grid(const int* __restrict__ coords, int N){
    int n = blockIdx.x*blockDim.x + threadIdx.x;
    if (n >= N) return;
    int b = coords[4*n], x = coords[4*n+1], y = coords[4*n+2], z = coords[4*n+3];
    d_grid[b*GRID3 + (x<<14) + (y<<7) + z] = n + 1;
}
__global__ void k_build_pairs(const int* __restrict__ coords, int N){
    int n = blockIdx.x*blockDim.x + threadIdx.x;
    bool valid = n < N;
    int nn = valid ? n : N - 1;
    int b = coords[4*nn], x = coords[4*nn+1], y = coords[4*nn+2], z = coords[4*nn+3];
    const int* gb = d_grid + b*GRID3;
    int lane = threadIdx.x & 31;
    unsigned lmlt = (1u << lane) - 1u;
    int kidx = 0;
    #pragma unroll
    for (int dx = -1; dx <= 1; dx++)
    #pragma unroll
    for (int dy = -1; dy <= 1; dy++)
    #pragma unroll
    for (int dz = -1; dz <= 1; dz++){
        if (kidx != 13){
            int nx = x+dx, ny = y+dy, nz = z+dz;
            bool ok = false; int j = 0;
            if (valid && nx>=0 && nx<GRIDD && ny>=0 && ny<GRIDD && nz>=0 && nz<GRIDD){
                j = gb[(nx<<14) + (ny<<7) + nz];
                ok = j > 0;
            }
            unsigned mask = __ballot_sync(0xffffffffu, ok);
            if (ok){
                int leader = __ffs(mask) - 1;
                int pos0 = 0;
                if (lane == leader) pos0 = atomicAdd(&d_cnt[kidx], __popc(mask));
                pos0 = __shfl_sync(mask, pos0, leader);
                int pos = pos0 + __popc(mask & lmlt);
                d_pairs[kidx*MAXN + pos] = make_int2(n, j-1);
            }
        }
        kidx++;
    }
}

// ================ persistent 64-row-tile HMMA GEMM, 2 CTAs/SM (center conv, plain stores) ================
#define G64_SMEM (384*SA*2)   // 104448 bytes

__global__ void __launch_bounds__(256, 2)
k_gemm_mma(const float* __restrict__ A, const __nv_bfloat16* __restrict__ Wsp,
           float* __restrict__ out, int N){
    extern __shared__ __nv_bfloat16 smb[];
    unsigned sb = smem_u32(smb);
    int tid = threadIdx.x;
    int wid = tid >> 5, lane = tid & 31;

    {
        const int4* src = (const int4*)Wsp;
        #pragma unroll
        for (int i = tid; i < 4096; i += 256){
            int sel = i >> 11, rem = i & 2047;
            int r = rem >> 4, c8 = rem & 15;
            __nv_bfloat16* dst = smb + (sel ? 256*SA : 128*SA) + r*SA + c8*8;
            *(int4*)dst = src[i];
        }
    }

    int mrow = (wid & 1)*32, ncol = (wid >> 1)*32;
    int arow = mrow + (lane & 15);
    int akoff = (lane >> 4)*8;
    int bi = lane >> 3;
    int brow = ncol + ((bi >> 1)*8) + (lane & 7);
    int bkoff = (bi & 1)*8;
    unsigned aAh = sb + (arow*SA + akoff)*2;
    unsigned aAl = sb + (64*SA + arow*SA + akoff)*2;
    unsigned aWh = sb + (128*SA + brow*SA + bkoff)*2;
    unsigned aWl = sb + (256*SA + brow*SA + bkoff)*2;

    int ntile = (N + 63) >> 6;
    int ar = tid >> 2, ac0 = (tid & 3)*32;

    for (int t = blockIdx.x; t < ntile; t += gridDim.x){
        int row0 = t*64;
        {
            int g = row0 + ar;
            #pragma unroll
            for (int cc = 0; cc < 32; cc += 4){
                int c = ac0 + cc;
                float4 v = make_float4(0.f,0.f,0.f,0.f);
                if (g < N) v = *(const float4*)&A[g*CH + c];
                split_store(smb, smb + 64*SA, ar*SA + c, v);
            }
        }
        __syncthreads();

        float acc[2][4][4];
        #pragma unroll
        for (int mi = 0; mi < 2; mi++)
            #pragma unroll
            for (int ni = 0; ni < 4; ni++)
                #pragma unroll
                for (int j = 0; j < 4; j++) acc[mi][ni][j] = 0.f;

        #pragma unroll
        for (int kk = 0; kk < 8; kk++){
            unsigned kb = kk*32;
            unsigned ah[2][4], al[2][4], bh[4][2], bl[4][2];
            #pragma unroll
            for (int mi = 0; mi < 2; mi++){
                ldsm4(ah[mi], aAh + mi*(16*SA*2) + kb);
                ldsm4(al[mi], aAl + mi*(16*SA*2) + kb);
            }
            {
                unsigned t0[4], t1[4];
                ldsm4(t0, aWh + kb);
                ldsm4(t1, aWh + 16*SA*2 + kb);
                bh[0][0]=t0[0]; bh[0][1]=t0[1]; bh[1][0]=t0[2]; bh[1][1]=t0[3];
                bh[2][0]=t1[0]; bh[2][1]=t1[1]; bh[3][0]=t1[2]; bh[3][1]=t1[3];
                ldsm4(t0, aWl + kb);
                ldsm4(t1, aWl + 16*SA*2 + kb);
                bl[0][0]=t0[0]; bl[0][1]=t0[1]; bl[1][0]=t0[2]; bl[1][1]=t0[3];
                bl[2][0]=t1[0]; bl[2][1]=t1[1]; bl[3][0]=t1[2]; bl[3][1]=t1[3];
            }
            #pragma unroll
            for (int mi = 0; mi < 2; mi++)
                #pragma unroll
                for (int ni = 0; ni < 4; ni++){
                    mma16816(acc[mi][ni], ah[mi], bh[ni]);
                    mma16816(acc[mi][ni], al[mi], bh[ni]);
                    mma16816(acc[mi][ni], ah[mi], bl[ni]);
                }
        }

        int rbase = row0 + mrow + (lane >> 2);
        int cbase = ncol + 2*(lane & 3);
        #pragma unroll
        for (int ni = 0; ni < 4; ni++){
            int col = cbase + ni*8;
            #pragma unroll
            for (int mi = 0; mi < 2; mi++){
                int g0 = rbase + mi*16;
                if (g0 < N)
                    *(float2*)&out[g0*CH + col] =
                        make_float2(acc[mi][ni][0], acc[mi][ni][1]);
                if (g0 + 8 < N)
                    *(float2*)&out[(g0+8)*CH + col] =
                        make_float2(acc[mi][ni][2], acc[mi][ni][3]);
            }
        }
        __syncthreads();
    }
}

// ---------------- sparse conv scatter: HMMA gather-GEMM, 2 CTAs/SM ----------------
__global__ void __launch_bounds__(256, 2)
k_conv_sparse(const float* __restrict__ feats){
    extern __shared__ __nv_bfloat16 smb[];
    unsigned sb = smem_u32(smb);
    int y = blockIdx.y;
    int kidx = y + (y >= 13);
    int cnt = d_cnt[kidx];
    int ntile = (cnt + 63) >> 6;
    if ((int)blockIdx.x >= ntile) return;
    int tid = threadIdx.x;
    int wid = tid >> 5, lane = tid & 31;

    {
        const int4* src = (const int4*)(d_Wcs + y*2*CH*CH);
        #pragma unroll
        for (int i = tid; i < 4096; i += 256){
            int sel = i >> 11, rem = i & 2047;
            int r = rem >> 4, c8 = rem & 15;
            __nv_bfloat16* dst = smb + (sel ? 256*SA : 128*SA) + r*SA + c8*8;
            *(int4*)dst = src[i];
        }
    }

    int mrow = (wid & 1)*32, ncol = (wid >> 1)*32;
    int arow = mrow + (lane & 15);
    int akoff = (lane >> 4)*8;
    int bi = lane >> 3;
    int brow = ncol + ((bi >> 1)*8) + (lane & 7);
    int bkoff = (bi & 1)*8;
    unsigned aAh = sb + (arow*SA + akoff)*2;
    unsigned aAl = sb + (64*SA + arow*SA + akoff)*2;
    unsigned aWh = sb + (128*SA + brow*SA + bkoff)*2;
    unsigned aWl = sb + (256*SA + brow*SA + bkoff)*2;

    int gr = tid >> 2, gc0 = (tid & 3)*32;

    for (int t = blockIdx.x; t < ntile; t += gridDim.x){
        int p0 = t << 6;
        int m = min(64, cnt - p0);
        __syncthreads();
        {
            int src = (gr < m) ? d_pairs[kidx*MAXN + p0 + gr].y : -1;
            #pragma unroll
            for (int cc = 0; cc < 32; cc += 4){
                int c = gc0 + cc;
                float4 v = make_float4(0.f,0.f,0.f,0.f);
                if (src >= 0) v = *(const float4*)&feats[src*CH + c];
                split_store(smb, smb + 64*SA, gr*SA + c, v);
            }
        }
        __syncthreads();

        float acc[2][4][4];
        #pragma unroll
        for (int mi = 0; mi < 2; mi++)
            #pragma unroll
            for (int ni = 0; ni < 4; ni++)
                #pragma unroll
                for (int j = 0; j < 4; j++) acc[mi][ni][j] = 0.f;

        #pragma unroll
        for (int kk = 0; kk < 8; kk++){
            unsigned kb = kk*32;
            unsigned ah[2][4], al[2][4], bh[4][2], bl[4][2];
            #pragma unroll
            for (int mi = 0; mi < 2; mi++){
                ldsm4(ah[mi], aAh + mi*(16*SA*2) + kb);
                ldsm4(al[mi], aAl + mi*(16*SA*2) + kb);
            }
            {
                unsigned t0[4], t1[4];
                ldsm4(t0, aWh + kb);
                ldsm4(t1, aWh + 16*SA*2 + kb);
                bh[0][0]=t0[0]; bh[0][1]=t0[1]; bh[1][0]=t0[2]; bh[1][1]=t0[3];
                bh[2][0]=t1[0]; bh[2][1]=t1[1]; bh[3][0]=t1[2]; bh[3][1]=t1[3];
                ldsm4(t0, aWl + kb);
                ldsm4(t1, aWl + 16*SA*2 + kb);
                bl[0][0]=t0[0]; bl[0][1]=t0[1]; bl[1][0]=t0[2]; bl[1][1]=t0[3];
                bl[2][0]=t1[0]; bl[2][1]=t1[1]; bl[3][0]=t1[2]; bl[3][1]=t1[3];
            }
            #pragma unroll
            for (int mi = 0; mi < 2; mi++)
                #pragma unroll
                for (int ni = 0; ni < 4; ni++){
                    mma16816(acc[mi][ni], ah[mi], bh[ni]);
                    mma16816(acc[mi][ni], al[mi], bh[ni]);
                    mma16816(acc[mi][ni], ah[mi], bl[ni]);
                }
        }

        int rb = mrow + (lane >> 2);
        int cb = ncol + 2*(lane & 3);
        int px[4];
        #pragma unroll
        for (int r4 = 0; r4 < 4; r4++){
            int row = rb + r4*8;
            px[r4] = (row < m) ? d_pairs[kidx*MAXN + p0 + row].x : -1;
        }
        #pragma unroll
        for (int ni = 0; ni < 4; ni++){
            int col = cb + ni*8;
            #pragma unroll
            for (int mi = 0; mi < 2; mi++){
                int p1 = px[mi*2], p2 = px[mi*2 + 1];
                if (p1 >= 0){
                    atomicAdd(&d_x[p1*CH + col],     acc[mi][ni][0]);
                    atomicAdd(&d_x[p1*CH + col + 1], acc[mi][ni][1]);
                }
                if (p2 >= 0){
                    atomicAdd(&d_x[p2*CH + col],     acc[mi][ni][2]);
                    atomicAdd(&d_x[p2*CH + col + 1], acc[mi][ni][3]);
                }
            }
        }
    }
}

// ---------------- merged mid: BN stats+finalize, psum, unset_grid ----------------
__global__ void k_mid(const float* __restrict__ gamma, const float* __restrict__ beta,
                      const float* __restrict__ probs, const int* __restrict__ coords,
                      int N, int nbbn, int npz){
    int bx = blockIdx.x, tid = threadIdx.x;
    if (bx < nbbn){
        int c = tid & 127, half = tid >> 7;
        int r0 = bx*256 + half*128;
        int lim = min(128, N - r0);
        float s = 0.f, q = 0.f;
        for (int r = 0; r < lim; r++){
            float v = d_x[(r0+r)*CH + c];
            s += v; q += v*v;
        }
        atomicAdd(&d_sum[c], s);
        atomicAdd(&d_sumsq[c], q);
        __shared__ unsigned lastv;
        __syncthreads();
        if (tid == 0){
            __threadfence();
            lastv = atomicAdd(&d_bnctr, 1u);
        }
        __syncthreads();
        if (lastv == (unsigned)(nbbn - 1)){
            if (tid < CH){
                float inv = 1.f/(float)N;
                float mu = d_sum[tid]*inv;
                float var = d_sumsq[tid]*inv - mu*mu;
                float a = gamma[tid]*rsqrtf(var + 1e-5f);
                d_bna[tid] = a;
                d_bnb[tid] = beta[tid] - mu*a;
            }
            if (tid == 0) d_bnctr = 0;
        }
    } else if (bx < nbbn + npz){
        int n0 = (bx - nbbn)*1000;
        int npb = N / NB;
        int b = n0 / npb;
        int k = tid & 31, slot = tid >> 5;
        float z = 0.f;
        for (int i = slot; i < 1000; i += 8)
            z += __expf(probs[(n0+i)*KP + k]);
        __shared__ float sr[8][KP];
        sr[slot][k] = z;
        __syncthreads();
        if (tid < KP){
            float zz = sr[0][tid];
            #pragma unroll
            for (int s2 = 1; s2 < 8; s2++) zz += sr[s2][tid];
            atomicAdd(&d_pz[b*KP + tid], zz);
        }
    } else {
        int n = (bx - nbbn - npz)*256 + tid;
        if (n < N){
            int b = coords[4*n], x = coords[4*n+1], y = coords[4*n+2], z = coords[4*n+3];
            d_grid[b*GRID3 + (x<<14) + (y<<7) + z] = 0;
        }
    }
}

// ---------------- ctx: 10-point rounds ----------------
__global__ void __launch_bounds__(256)
k_ctx(const int* __restrict__ coords, const float* __restrict__ probs, int N){
    __shared__ float wsh[2][10][KP];
    __shared__ float szs[KP];
    int n0 = blockIdx.x*200;
    if (n0 >= N) return;
    int b = coords[4*n0];
    int tid = threadIdx.x;
    int half = tid >> 7, t = tid & 127;
    if (tid < KP) szs[tid] = d_pz[b*KP + tid];
    float ba = d_bna[t], bb = d_bnb[t];
    __syncthreads();
    float acc[KP];
    #pragma unroll
    for (int k = 0; k < KP; k++) acc[k] = 0.f;
    int base = n0 + half*100;
    for (int g = 0; g < 100; g += 10){
        {
            int p = t >> 5, k = t & 31;
            int n = base + g + p;
            wsh[half][p][k] = (n < N) ? __expf(probs[n*KP + k]) / szs[k] : 0.f;
        }
        {
            int p = 4 + (t >> 5), k = t & 31;
            int n = base + g + p;
            wsh[half][p][k] = (n < N) ? __expf(probs[n*KP + k]) / szs[k] : 0.f;
        }
        if (t < 64){
            int p = 8 + (t >> 5), k = t & 31;
            int n = base + g + p;
            wsh[half][p][k] = (n < N) ? __expf(probs[n*KP + k]) / szs[k] : 0.f;
        }
        __syncthreads();
        #pragma unroll
        for (int p2 = 0; p2 < 10; p2++){
            int n2 = base + g + p2;
            float xv = (n2 < N) ? fmaxf(fmaf(d_x[n2*CH + t], ba, bb), 0.f) : 0.f;
            #pragma unroll
            for (int k2 = 0; k2 < KP; k2++) acc[k2] += wsh[half][p2][k2]*xv;
        }
        __syncthreads();
    }
    #pragma unroll
    for (int k2 = 0; k2 < KP; k2++)
        atomicAdd(&d_ctx[(b*KP+k2)*CH + t], acc[k2]);
}

// ---------------- K/V projections ----------------
__global__ void k_kvproj(const float* __restrict__ ipb){
    int row = blockIdx.x;
    int co = threadIdx.x;
    __shared__ float cr[CH];
    cr[co] = d_ctx[row*CH + co];
    __syncthreads();
    float ak = 0.f, av = 0.f;
    #pragma unroll 8
    for (int ci = 0; ci < CH; ci++){
        float c = cr[ci];
        ak += c*d_WT[CH*CH   + ci*CH + co];
        av += c*d_WT[2*CH*CH + ci*CH + co];
    }
    d_kh[row*CH + co] = ak + ipb[CH + co];
    d_vh[row*CH + co] = av + ipb[2*CH + co];
}

// ======== fused q-GEMM + attention + output GEMM ========
#define FQ_R1 0
#define FQ_R2 69632
#define FQ_KV 139264
#define FQ_TOT 172032

__global__ void __launch_bounds__(256, 1)
k_attn_out(const int* __restrict__ coords, const float* __restrict__ ipb,
           float* __restrict__ out, int N){
    extern __shared__ char sm[];
    unsigned sb = smem_u32(sm);
    __nv_bfloat16* r1h = (__nv_bfloat16*)(sm + FQ_R1);
    __nv_bfloat16* r1l = r1h + 128*SA;
    __nv_bfloat16* r2h = (__nv_bfloat16*)(sm + FQ_R2);
    __nv_bfloat16* r2l = r2h + 128*SA;
    float* qsm = (float*)(sm + FQ_R1);
    float* sK = (float*)(sm + FQ_KV);
    float* sV = sK + KP*CH;
    int tid = threadIdx.x;
    int wid = tid >> 5, lane = tid & 31;
    int n0 = blockIdx.x*128;
    if (n0 >= N) return;
    int b0 = coords[4*n0];
    int b1 = coords[4*min(n0 + 127, N - 1)];

    {
        int r = tid >> 1, c0 = (tid & 1)*64;
        int g = n0 + r;
        #pragma unroll
        for (int cc = 0; cc < 64; cc += 4){
            int c = c0 + cc;
            float4 v = make_float4(0.f,0.f,0.f,0.f);
            if (g < N) v = *(const float4*)&d_x[g*CH + c];
            v.x = fmaxf(fmaf(v.x, d_bna[c  ], d_bnb[c  ]), 0.f);
            v.y = fmaxf(fmaf(v.y, d_bna[c+1], d_bnb[c+1]), 0.f);
            v.z = fmaxf(fmaf(v.z, d_bna[c+2], d_bnb[c+2]), 0.f);
            v.w = fmaxf(fmaf(v.w, d_bna[c+3], d_bnb[c+3]), 0.f);
            split_store(r1h, r1l, r*SA + c, v);
        }
    }
    {
        const int4* src = (const int4*)(d_Wb + 2*CH*CH);
        #pragma unroll
        for (int i = tid; i < 4096; i += 256){
            int sel = i >> 11, rem = i & 2047;
            int r = rem >> 4, c8 = rem & 15;
            __nv_bfloat16* dst = (sel ? r2l : r2h) + r*SA + c8*8;
            *(int4*)dst = src[i];
        }
    }
    for (int i = tid; i < KP*CH/4; i += 256){
        ((float4*)sK)[i] = ((const float4*)(d_kh + b0*KP*CH))[i];
        ((float4*)sV)[i] = ((const float4*)(d_vh + b0*KP*CH))[i];
    }
    __syncthreads();

    float qacc[4][4][4];
    mma_main_128(sb + FQ_R1, sb + FQ_R1 + 128*SA*2, sb + FQ_R2, sb + FQ_R2 + 128*SA*2,
                 wid, lane, qacc);
    __syncthreads();
    {
        int mrow = (wid & 1)*64, ncol = (wid >> 1)*32;
        int rbase = mrow + (lane >> 2);
        int cbase = ncol + 2*(lane & 3);
        #pragma unroll
        for (int ni = 0; ni < 4; ni++){
            int col = cbase + ni*8;
            float b0f = ipb[col], b1f = ipb[col+1];
            #pragma unroll
            for (int mi = 0; mi < 4; mi++){
                int r0 = rbase + mi*16;
                *(float2*)&qsm[r0*132 + col] =
                    make_float2(0.25f*(qacc[mi][ni][0]+b0f), 0.25f*(qacc[mi][ni][1]+b1f));
                *(float2*)&qsm[(r0+8)*132 + col] =
                    make_float2(0.25f*(qacc[mi][ni][2]+b0f), 0.25f*(qacc[mi][ni][3]+b1f));
            }
        }
    }
    __syncthreads();

    for (int pp = 0; pp < 16; pp += 2){
        int r1 = wid*16 + pp;
        int n1 = n0 + r1, n2 = n1 + 1;
        bool one = (n1 < N), two = (n2 < N);
        int bsel = (one && coords[4*n1] != b0) ? 1 : 0;
        float4 q1 = *(const float4*)&qsm[r1*132 + 4*lane];
        float4 q2 = *(const float4*)&qsm[(r1+1)*132 + 4*lane];
        float s1[KP], s2[KP];
        #pragma unroll
        for (int k = 0; k < KP; k++){
            float4 kv = bsel ? *(const float4*)&d_kh[(b1*KP + k)*CH + 4*lane]
                             : *(const float4*)&sK[k*CH + 4*lane];
            s1[k] = q1.x*kv.x + q1.y*kv.y + q1.z*kv.z + q1.w*kv.w;
            s2[k] = q2.x*kv.x + q2.y*kv.y + q2.z*kv.z + q2.w*kv.w;
        }
        #pragma unroll
        for (int k = 0; k < KP; k++){
            s1[k] += __shfl_xor_sync(0xffffffffu, s1[k], 1);
            s1[k] += __shfl_xor_sync(0xffffffffu, s1[k], 2);
            s2[k] += __shfl_xor_sync(0xffffffffu, s2[k], 1);
            s2[k] += __shfl_xor_sync(0xffffffffu, s2[k], 2);
        }
        float m1 = -3.4e38f, m2 = -3.4e38f;
        #pragma unroll
        for (int k = 0; k < KP; k++){ m1 = fmaxf(m1, s1[k]); m2 = fmaxf(m2, s2[k]); }
        float z1 = 0.f, z2 = 0.f;
        #pragma unroll
        for (int k = 0; k < KP; k++){
            s1[k] = __expf(s1[k] - m1); z1 += s1[k];
            s2[k] = __expf(s2[k] - m2); z2 += s2[k];
        }
        float i1 = 1.f/z1, i2 = 1.f/z2;
        float4 o1 = make_float4(0,0,0,0), o2 = make_float4(0,0,0,0);
        #pragma unroll
        for (int k = 0; k < KP; k++){
            float4 vvv = bsel ? *(const float4*)&d_vh[(b1*KP + k)*CH + 4*lane]
                              : *(const float4*)&sV[k*CH + 4*lane];
            o1.x += s1[k]*vvv.x; o1.y += s1[k]*vvv.y; o1.z += s1[k]*vvv.z; o1.w += s1[k]*vvv.w;
            o2.x += s2[k]*vvv.x; o2.y += s2[k]*vvv.y; o2.z += s2[k]*vvv.z; o2.w += s2[k]*vvv.w;
        }
        if (!one){ o1 = make_float4(0,0,0,0); i1 = 0.f; }
        if (!two){ o2 = make_float4(0,0,0,0); i2 = 0.f; }
        o1.x*=i1; o1.y*=i1; o1.z*=i1; o1.w*=i1;
        o2.x*=i2; o2.y*=i2; o2.z*=i2; o2.w*=i2;
        split_store(r2h, r2l, r1*SA + 4*lane, o1);
        split_store(r2h, r2l, (r1+1)*SA + 4*lane, o2);
    }
    __syncthreads();

    {
        const int4* src = (const int4*)(d_Wb + 4*CH*CH);
        #pragma unroll
        for (int i = tid; i < 4096; i += 256){
            int sel = i >> 11, rem = i & 2047;
            int r = rem >> 4, c8 = rem & 15;
            __nv_bfloat16* dst = (sel ? r1l : r1h) + r*SA + c8*8;
            *(int4*)dst = src[i];
        }
    }
    __syncthreads();
    float acc[4][4][4];
    mma_main_128(sb + FQ_R2, sb + FQ_R2 + 128*SA*2, sb + FQ_R1, sb + FQ_R1 + 128*SA*2,
                 wid, lane, acc);
    {
        int mrow = (wid & 1)*64, ncol = (wid >> 1)*32;
        int rbase = n0 + mrow + (lane >> 2);
        int cbase = ncol + 2*(lane & 3);
        #pragma unroll
        for (int ni = 0; ni < 4; ni++){
            int col = cbase + ni*8;
            float b0f = d_b2[col], b1f = d_b2[col+1];
            #pragma unroll
            for (int mi = 0; mi < 4; mi++){
                int g0 = rbase + mi*16;
                if (g0 < N)
                    *(float2*)&out[g0*CH + col] =
                        make_float2(acc[mi][ni][0]+b0f, acc[mi][ni][1]+b1f);
                if (g0 + 8 < N)
                    *(float2*)&out[(g0+8)*CH + col] =
                        make_float2(acc[mi][ni][2]+b0f, acc[mi][ni][3]+b1f);
            }
        }
    }
}

extern "C" void kernel_launch(void* const* d_in, const int* in_sizes, int n_in,
                              void* d_out, int out_size){
    const float* feats  = (const float*)d_in[0];
    const float* probs  = (const float*)d_in[1];
    const float* conv_w = (const float*)d_in[2];
    const float* gamma  = (const float*)d_in[3];
    const float* beta   = (const float*)d_in[4];
    const float* ipw    = (const float*)d_in[5];
    const float* ipb    = (const float*)d_in[6];
    const float* opw    = (const float*)d_in[7];
    const float* opb    = (const float*)d_in[8];
    const float* bw     = (const float*)d_in[9];
    const int*   coords = (const int*)d_in[10];
    float* out = (float*)d_out;
    int N = in_sizes[0] / CH;

    static float* dx_p=nullptr;
    static __nv_bfloat16* dwb_p=nullptr;
    if (!dx_p){
        cudaGetSymbolAddress((void**)&dx_p,  d_x);
        cudaGetSymbolAddress((void**)&dwb_p, d_Wb);
        cudaFuncSetAttribute(k_gemm_mma,    cudaFuncAttributeMaxDynamicSharedMemorySize, G64_SMEM);
        cudaFuncSetAttribute(k_attn_out,    cudaFuncAttributeMaxDynamicSharedMemorySize, FQ_TOT);
        cudaFuncSetAttribute(k_conv_sparse, cudaFuncAttributeMaxDynamicSharedMemorySize, G64_SMEM);
    }
    int nb256 = (N + 255)/256;
    int nbA = (N + 127)/128;
    int ntile = (N + 63)/64;
    int gG = min(296, ntile);
    int npz = N/1000;

    k_prep<<<401, 256>>>(ipw, conv_w, bw, opw, opb);
    k_build_grid<<<nb256, 256>>>(coords, N);
    k_build_pairs<<<nb256, 256>>>(coords, N);
    k_gemm_mma<<<gG, 256, G64_SMEM>>>(feats, dwb_p, dx_p, N);
    k_conv_sparse<<<dim3(8, 26), 256, G64_SMEM>>>(feats);
    k_mid<<<nb256 + npz + nb256, 256>>>(gamma, beta, probs, coords, N, nb256, npz);
    k_ctx<<<(N+199)/200, 256>>>(coords, probs, N);
    k_kvproj<<<NB*KP, 128>>>(ipb);
    k_attn_out<<<nbA, 256, FQ_TOT>>>(coords, ipb, out, N);
}

// round 17
// speedup vs baseline: 1.4803x; 1.0233x over previous
#include <cuda_runtime.h>
#include <cuda_bf16.h>
#include <math.h>

#define GRIDD 128
#define GRID3 (GRIDD*GRIDD*GRIDD)
#define NB 4
#define CH 128
#define KP 32
#define MAXN 100352
#define SA 136   // smem row stride in bf16

static __device__ int    d_grid[NB*GRID3];
static __device__ int2   d_pairs[27*MAXN];
static __device__ int    d_cnt[27];
static __device__ float  d_x[MAXN*CH];
static __device__ float  d_sum[CH];
static __device__ float  d_sumsq[CH];
static __device__ float  d_bna[CH];
static __device__ float  d_bnb[CH];
static __device__ unsigned d_bnctr;
static __device__ float  d_pz[NB*KP];
static __device__ float  d_ctx[NB*KP*CH];
static __device__ float  d_kh[NB*KP*CH];
static __device__ float  d_vh[NB*KP*CH];
static __device__ float  d_WT[3*CH*CH];
static __device__ float  d_b2[CH];
static __device__ __nv_bfloat16 d_Wb[3*2*CH*CH];    // 0=Wc, 1=Wq, 2=W2fold; {hi,lo} [co][ci]
static __device__ __nv_bfloat16 d_Wcs[26*2*CH*CH];  // 26 off-center conv weights, {hi,lo} [co][ci]

__device__ __forceinline__ unsigned smem_u32(const void* p){
    unsigned a;
    asm("{ .reg .u64 t; cvta.to.shared.u64 t, %1; cvt.u32.u64 %0, t; }" : "=r"(a) : "l"(p));
    return a;
}
__device__ __forceinline__ void ldsm4(unsigned* r, unsigned addr){
    asm volatile("ldmatrix.sync.aligned.m8n8.x4.shared.b16 {%0,%1,%2,%3}, [%4];"
        : "=r"(r[0]), "=r"(r[1]), "=r"(r[2]), "=r"(r[3]) : "r"(addr));
}
__device__ __forceinline__ void mma16816(float* d, const unsigned* a, const unsigned* b){
    asm volatile("mma.sync.aligned.m16n8k16.row.col.f32.bf16.bf16.f32 "
        "{%0,%1,%2,%3}, {%4,%5,%6,%7}, {%8,%9}, {%0,%1,%2,%3};"
        : "+f"(d[0]), "+f"(d[1]), "+f"(d[2]), "+f"(d[3])
        : "r"(a[0]), "r"(a[1]), "r"(a[2]), "r"(a[3]), "r"(b[0]), "r"(b[1]));
}
__device__ __forceinline__ void split_store(__nv_bfloat16* hi, __nv_bfloat16* lo,
                                            int base, float4 v){
    __nv_bfloat16 hx=__float2bfloat16_rn(v.x), hy=__float2bfloat16_rn(v.y);
    __nv_bfloat16 hz=__float2bfloat16_rn(v.z), hw=__float2bfloat16_rn(v.w);
    __nv_bfloat162 h01; h01.x=hx; h01.y=hy;
    __nv_bfloat162 h23; h23.x=hz; h23.y=hw;
    *(__nv_bfloat162*)(hi + base)     = h01;
    *(__nv_bfloat162*)(hi + base + 2) = h23;
    __nv_bfloat162 l01, l23;
    l01.x = __float2bfloat16_rn(v.x - __bfloat162float(hx));
    l01.y = __float2bfloat16_rn(v.y - __bfloat162float(hy));
    l23.x = __float2bfloat16_rn(v.z - __bfloat162float(hz));
    l23.y = __float2bfloat16_rn(v.w - __bfloat162float(hw));
    *(__nv_bfloat162*)(lo + base)     = l01;
    *(__nv_bfloat162*)(lo + base + 2) = l23;
}
__device__ __forceinline__ void split2(float a, __nv_bfloat16* hi, __nv_bfloat16* lo, int idx){
    __nv_bfloat16 h = __float2bfloat16_rn(a);
    hi[idx] = h;
    lo[idx] = __float2bfloat16_rn(a - __bfloat162float(h));
}

// 16-warp HMMA mainloop over a 128x128 tile: warp tile 32x32, acc[2][4][4].
__device__ __forceinline__ void mma_main_16w(
    unsigned sb_ah, unsigned sb_al, unsigned sb_wh, unsigned sb_wl,
    int wid, int lane, float acc[2][4][4])
{
    int mrow = (wid & 3)*32, ncol = (wid >> 2)*32;
    #pragma unroll
    for (int mi = 0; mi < 2; mi++)
        #pragma unroll
        for (int ni = 0; ni < 4; ni++)
            #pragma unroll
            for (int j = 0; j < 4; j++) acc[mi][ni][j] = 0.f;

    int arow = mrow + (lane & 15);
    int akoff = (lane >> 4)*8;
    int bi = lane >> 3;
    int brow = ncol + ((bi >> 1)*8) + (lane & 7);
    int bkoff = (bi & 1)*8;
    unsigned aAh = sb_ah + (arow*SA + akoff)*2;
    unsigned aAl = sb_al + (arow*SA + akoff)*2;
    unsigned aWh = sb_wh + (brow*SA + bkoff)*2;
    unsigned aWl = sb_wl + (brow*SA + bkoff)*2;

    #pragma unroll
    for (int kk = 0; kk < 8; kk++){
        unsigned kb = kk*32;
        unsigned ah[2][4], al[2][4], bh[4][2], bl[4][2];
        #pragma unroll
        for (int mi = 0; mi < 2; mi++){
            ldsm4(ah[mi], aAh + mi*(16*SA*2) + kb);
            ldsm4(al[mi], aAl + mi*(16*SA*2) + kb);
        }
        {
            unsigned t0[4], t1[4];
            ldsm4(t0, aWh + kb);
            ldsm4(t1, aWh + 16*SA*2 + kb);
            bh[0][0]=t0[0]; bh[0][1]=t0[1]; bh[1][0]=t0[2]; bh[1][1]=t0[3];
            bh[2][0]=t1[0]; bh[2][1]=t1[1]; bh[3][0]=t1[2]; bh[3][1]=t1[3];
            ldsm4(t0, aWl + kb);
            ldsm4(t1, aWl + 16*SA*2 + kb);
            bl[0][0]=t0[0]; bl[0][1]=t0[1]; bl[1][0]=t0[2]; bl[1][1]=t0[3];
            bl[2][0]=t1[0]; bl[2][1]=t1[1]; bl[3][0]=t1[2]; bl[3][1]=t1[3];
        }
        #pragma unroll
        for (int mi = 0; mi < 2; mi++)
            #pragma unroll
            for (int ni = 0; ni < 4; ni++){
                mma16816(acc[mi][ni], ah[mi], bh[ni]);
                mma16816(acc[mi][ni], al[mi], bh[ni]);
                mma16816(acc[mi][ni], ah[mi], bl[ni]);
            }
    }
}

// ---------------- fused prep (+ coalesced conv weight transpose-splits) ----------------
__global__ void k_prep(const float* __restrict__ ipw, const float* __restrict__ conv_w,
                       const float* __restrict__ bw, const float* __restrict__ wop,
                       const float* __restrict__ bop){
    __shared__ float we[CH];
    __shared__ float tile[CH][17];
    int bx = blockIdx.x, tid = threadIdx.x;
    if (bx < 128){
        if (tid < CH) we[tid] = bw[bx*256 + tid] + bw[bx*256 + 128 + tid];
        __syncthreads();
        if (tid < CH){
            float a = 0.f;
            #pragma unroll 8
            for (int t = 0; t < CH; t++) a += we[t]*wop[t*CH + tid];
            split2(a, d_Wb + 4*CH*CH, d_Wb + 5*CH*CH, bx*CH + tid);
            if (tid == 0){
                float s = 0.f;
                for (int t = 0; t < CH; t++) s += we[t]*bop[t];
                d_b2[bx] = s;
            }
        }
    } else if (bx < 192){
        int i0 = (bx - 128)*256 + tid;
        split2(ipw[i0], d_Wb + 2*CH*CH, d_Wb + 3*CH*CH, i0);
        {
            int o = i0 >> 7, c = i0 & 127;
            split2(conv_w[13*CH*CH + c*CH + o], d_Wb, d_Wb + CH*CH, i0);
        }
        {
            int ci = i0 >> 7, co = i0 & 127;
            d_WT[CH*CH   + i0] = ipw[(CH   + co)*CH + ci];
            d_WT[2*CH*CH + i0] = ipw[(2*CH + co)*CH + ci];
        }
    } else if (bx == 192){
        for (int i = tid; i < NB*KP*CH; i += 256) d_ctx[i] = 0.f;
        if (tid < CH){ d_sum[tid]=0.f; d_sumsq[tid]=0.f; }
        if (tid < NB*KP) d_pz[tid]=0.f;
        if (tid < 27) d_cnt[tid]=0;
    } else {
        int idx = bx - 193;
        int y = idx >> 3, c0 = (idx & 7)*16;
        int kidx = y + (y >= 13);
        const float* W = conv_w + kidx*CH*CH;
        __nv_bfloat16* hi = d_Wcs + y*2*CH*CH;
        __nv_bfloat16* lo = hi + CH*CH;
        for (int i = tid; i < CH*16; i += 256){
            int ci = i >> 4, cc = i & 15;
            tile[ci][cc] = W[ci*CH + c0 + cc];
        }
        __syncthreads();
        for (int i = tid; i < 16*CH; i += 256){
            int cc = i >> 7, ci = i & 127;
            split2(tile[ci][cc], hi, lo, (c0 + cc)*CH + ci);
        }
    }
}

// ---------------- rulebook ----------------
__global__ void k_build_grid(const int* __restrict__ coords, int N){
    int n = blockIdx.x*blockDim.x + threadIdx.x;
    if (n >= N) return;
    int b = coords[4*n], x = coords[4*n+1], y = coords[4*n+2], z = coords[4*n+3];
    d_grid[b*GRID3 + (x<<14) + (y<<7) + z] = n + 1;
}
__global__ void k_build_pairs(const int* __restrict__ coords, int N){
    int n = blockIdx.x*blockDim.x + threadIdx.x;
    bool valid = n < N;
    int nn = valid ? n : N - 1;
    int b = coords[4*nn], x = coords[4*nn+1], y = coords[4*nn+2], z = coords[4*nn+3];
    const int* gb = d_grid + b*GRID3;
    int lane = threadIdx.x & 31;
    unsigned lmlt = (1u << lane) - 1u;
    int kidx = 0;
    #pragma unroll
    for (int dx = -1; dx <= 1; dx++)
    #pragma unroll
    for (int dy = -1; dy <= 1; dy++)
    #pragma unroll
    for (int dz = -1; dz <= 1; dz++){
        if (kidx != 13){
            int nx = x+dx, ny = y+dy, nz = z+dz;
            bool ok = false; int j = 0;
            if (valid && nx>=0 && nx<GRIDD && ny>=0 && ny<GRIDD && nz>=0 && nz<GRIDD){
                j = gb[(nx<<14) + (ny<<7) + nz];
                ok = j > 0;
            }
            unsigned mask = __ballot_sync(0xffffffffu, ok);
            if (ok){
                int leader = __ffs(mask) - 1;
                int pos0 = 0;
                if (lane == leader) pos0 = atomicAdd(&d_cnt[kidx], __popc(mask));
                pos0 = __shfl_sync(mask, pos0, leader);
                int pos = pos0 + __popc(mask & lmlt);
                d_pairs[kidx*MAXN + pos] = make_int2(n, j-1);
            }
        }
        kidx++;
    }
}

// ================ persistent 64-row-tile HMMA GEMM, 2 CTAs/SM (center conv, plain stores) ================
#define G64_SMEM (384*SA*2)   // 104448 bytes

__global__ void __launch_bounds__(256, 2)
k_gemm_mma(const float* __restrict__ A, const __nv_bfloat16* __restrict__ Wsp,
           float* __restrict__ out, int N){
    extern __shared__ __nv_bfloat16 smb[];
    unsigned sb = smem_u32(smb);
    int tid = threadIdx.x;
    int wid = tid >> 5, lane = tid & 31;

    {
        const int4* src = (const int4*)Wsp;
        #pragma unroll
        for (int i = tid; i < 4096; i += 256){
            int sel = i >> 11, rem = i & 2047;
            int r = rem >> 4, c8 = rem & 15;
            __nv_bfloat16* dst = smb + (sel ? 256*SA : 128*SA) + r*SA + c8*8;
            *(int4*)dst = src[i];
        }
    }

    int mrow = (wid & 1)*32, ncol = (wid >> 1)*32;
    int arow = mrow + (lane & 15);
    int akoff = (lane >> 4)*8;
    int bi = lane >> 3;
    int brow = ncol + ((bi >> 1)*8) + (lane & 7);
    int bkoff = (bi & 1)*8;
    unsigned aAh = sb + (arow*SA + akoff)*2;
    unsigned aAl = sb + (64*SA + arow*SA + akoff)*2;
    unsigned aWh = sb + (128*SA + brow*SA + bkoff)*2;
    unsigned aWl = sb + (256*SA + brow*SA + bkoff)*2;

    int ntile = (N + 63) >> 6;
    int ar = tid >> 2, ac0 = (tid & 3)*32;

    for (int t = blockIdx.x; t < ntile; t += gridDim.x){
        int row0 = t*64;
        {
            int g = row0 + ar;
            #pragma unroll
            for (int cc = 0; cc < 32; cc += 4){
                int c = ac0 + cc;
                float4 v = make_float4(0.f,0.f,0.f,0.f);
                if (g < N) v = *(const float4*)&A[g*CH + c];
                split_store(smb, smb + 64*SA, ar*SA + c, v);
            }
        }
        __syncthreads();

        float acc[2][4][4];
        #pragma unroll
        for (int mi = 0; mi < 2; mi++)
            #pragma unroll
            for (int ni = 0; ni < 4; ni++)
                #pragma unroll
                for (int j = 0; j < 4; j++) acc[mi][ni][j] = 0.f;

        #pragma unroll
        for (int kk = 0; kk < 8; kk++){
            unsigned kb = kk*32;
            unsigned ah[2][4], al[2][4], bh[4][2], bl[4][2];
            #pragma unroll
            for (int mi = 0; mi < 2; mi++){
                ldsm4(ah[mi], aAh + mi*(16*SA*2) + kb);
                ldsm4(al[mi], aAl + mi*(16*SA*2) + kb);
            }
            {
                unsigned t0[4], t1[4];
                ldsm4(t0, aWh + kb);
                ldsm4(t1, aWh + 16*SA*2 + kb);
                bh[0][0]=t0[0]; bh[0][1]=t0[1]; bh[1][0]=t0[2]; bh[1][1]=t0[3];
                bh[2][0]=t1[0]; bh[2][1]=t1[1]; bh[3][0]=t1[2]; bh[3][1]=t1[3];
                ldsm4(t0, aWl + kb);
                ldsm4(t1, aWl + 16*SA*2 + kb);
                bl[0][0]=t0[0]; bl[0][1]=t0[1]; bl[1][0]=t0[2]; bl[1][1]=t0[3];
                bl[2][0]=t1[0]; bl[2][1]=t1[1]; bl[3][0]=t1[2]; bl[3][1]=t1[3];
            }
            #pragma unroll
            for (int mi = 0; mi < 2; mi++)
                #pragma unroll
                for (int ni = 0; ni < 4; ni++){
                    mma16816(acc[mi][ni], ah[mi], bh[ni]);
                    mma16816(acc[mi][ni], al[mi], bh[ni]);
                    mma16816(acc[mi][ni], ah[mi], bl[ni]);
                }
        }

        int rbase = row0 + mrow + (lane >> 2);
        int cbase = ncol + 2*(lane & 3);
        #pragma unroll
        for (int ni = 0; ni < 4; ni++){
            int col = cbase + ni*8;
            #pragma unroll
            for (int mi = 0; mi < 2; mi++){
                int g0 = rbase + mi*16;
                if (g0 < N)
                    *(float2*)&out[g0*CH + col] =
                        make_float2(acc[mi][ni][0], acc[mi][ni][1]);
                if (g0 + 8 < N)
                    *(float2*)&out[(g0+8)*CH + col] =
                        make_float2(acc[mi][ni][2], acc[mi][ni][3]);
            }
        }
        __syncthreads();
    }
}

// ---------------- sparse conv scatter: HMMA gather-GEMM, 2 CTAs/SM ----------------
__global__ void __launch_bounds__(256, 2)
k_conv_sparse(const float* __restrict__ feats){
    extern __shared__ __nv_bfloat16 smb[];
    unsigned sb = smem_u32(smb);
    int y = blockIdx.y;
    int kidx = y + (y >= 13);
    int cnt = d_cnt[kidx];
    int ntile = (cnt + 63) >> 6;
    if ((int)blockIdx.x >= ntile) return;
    int tid = threadIdx.x;
    int wid = tid >> 5, lane = tid & 31;

    {
        const int4* src = (const int4*)(d_Wcs + y*2*CH*CH);
        #pragma unroll
        for (int i = tid; i < 4096; i += 256){
            int sel = i >> 11, rem = i & 2047;
            int r = rem >> 4, c8 = rem & 15;
            __nv_bfloat16* dst = smb + (sel ? 256*SA : 128*SA) + r*SA + c8*8;
            *(int4*)dst = src[i];
        }
    }

    int mrow = (wid & 1)*32, ncol = (wid >> 1)*32;
    int arow = mrow + (lane & 15);
    int akoff = (lane >> 4)*8;
    int bi = lane >> 3;
    int brow = ncol + ((bi >> 1)*8) + (lane & 7);
    int bkoff = (bi & 1)*8;
    unsigned aAh = sb + (arow*SA + akoff)*2;
    unsigned aAl = sb + (64*SA + arow*SA + akoff)*2;
    unsigned aWh = sb + (128*SA + brow*SA + bkoff)*2;
    unsigned aWl = sb + (256*SA + brow*SA + bkoff)*2;

    int gr = tid >> 2, gc0 = (tid & 3)*32;

    for (int t = blockIdx.x; t < ntile; t += gridDim.x){
        int p0 = t << 6;
        int m = min(64, cnt - p0);
        __syncthreads();
        {
            int src = (gr < m) ? d_pairs[kidx*MAXN + p0 + gr].y : -1;
            #pragma unroll
            for (int cc = 0; cc < 32; cc += 4){
                int c = gc0 + cc;
                float4 v = make_float4(0.f,0.f,0.f,0.f);
                if (src >= 0) v = *(const float4*)&feats[src*CH + c];
                split_store(smb, smb + 64*SA, gr*SA + c, v);
            }
        }
        __syncthreads();

        float acc[2][4][4];
        #pragma unroll
        for (int mi = 0; mi < 2; mi++)
            #pragma unroll
            for (int ni = 0; ni < 4; ni++)
                #pragma unroll
                for (int j = 0; j < 4; j++) acc[mi][ni][j] = 0.f;

        #pragma unroll
        for (int kk = 0; kk < 8; kk++){
            unsigned kb = kk*32;
            unsigned ah[2][4], al[2][4], bh[4][2], bl[4][2];
            #pragma unroll
            for (int mi = 0; mi < 2; mi++){
                ldsm4(ah[mi], aAh + mi*(16*SA*2) + kb);
                ldsm4(al[mi], aAl + mi*(16*SA*2) + kb);
            }
            {
                unsigned t0[4], t1[4];
                ldsm4(t0, aWh + kb);
                ldsm4(t1, aWh + 16*SA*2 + kb);
                bh[0][0]=t0[0]; bh[0][1]=t0[1]; bh[1][0]=t0[2]; bh[1][1]=t0[3];
                bh[2][0]=t1[0]; bh[2][1]=t1[1]; bh[3][0]=t1[2]; bh[3][1]=t1[3];
                ldsm4(t0, aWl + kb);
                ldsm4(t1, aWl + 16*SA*2 + kb);
                bl[0][0]=t0[0]; bl[0][1]=t0[1]; bl[1][0]=t0[2]; bl[1][1]=t0[3];
                bl[2][0]=t1[0]; bl[2][1]=t1[1]; bl[3][0]=t1[2]; bl[3][1]=t1[3];
            }
            #pragma unroll
            for (int mi = 0; mi < 2; mi++)
                #pragma unroll
                for (int ni = 0; ni < 4; ni++){
                    mma16816(acc[mi][ni], ah[mi], bh[ni]);
                    mma16816(acc[mi][ni], al[mi], bh[ni]);
                    mma16816(acc[mi][ni], ah[mi], bl[ni]);
                }
        }

        int rb = mrow + (lane >> 2);
        int cb = ncol + 2*(lane & 3);
        int px[4];
        #pragma unroll
        for (int r4 = 0; r4 < 4; r4++){
            int row = rb + r4*8;
            px[r4] = (row < m) ? d_pairs[kidx*MAXN + p0 + row].x : -1;
        }
        #pragma unroll
        for (int ni = 0; ni < 4; ni++){
            int col = cb + ni*8;
            #pragma unroll
            for (int mi = 0; mi < 2; mi++){
                int p1 = px[mi*2], p2 = px[mi*2 + 1];
                if (p1 >= 0){
                    atomicAdd(&d_x[p1*CH + col],     acc[mi][ni][0]);
                    atomicAdd(&d_x[p1*CH + col + 1], acc[mi][ni][1]);
                }
                if (p2 >= 0){
                    atomicAdd(&d_x[p2*CH + col],     acc[mi][ni][2]);
                    atomicAdd(&d_x[p2*CH + col + 1], acc[mi][ni][3]);
                }
            }
        }
    }
}

// ---------------- merged mid: BN stats+finalize, psum, unset_grid ----------------
__global__ void k_mid(const float* __restrict__ gamma, const float* __restrict__ beta,
                      const float* __restrict__ probs, const int* __restrict__ coords,
                      int N, int nbbn, int npz){
    int bx = blockIdx.x, tid = threadIdx.x;
    if (bx < nbbn){
        int c = tid & 127, half = tid >> 7;
        int r0 = bx*256 + half*128;
        int lim = min(128, N - r0);
        float s = 0.f, q = 0.f;
        for (int r = 0; r < lim; r++){
            float v = d_x[(r0+r)*CH + c];
            s += v; q += v*v;
        }
        atomicAdd(&d_sum[c], s);
        atomicAdd(&d_sumsq[c], q);
        __shared__ unsigned lastv;
        __syncthreads();
        if (tid == 0){
            __threadfence();
            lastv = atomicAdd(&d_bnctr, 1u);
        }
        __syncthreads();
        if (lastv == (unsigned)(nbbn - 1)){
            if (tid < CH){
                float inv = 1.f/(float)N;
                float mu = d_sum[tid]*inv;
                float var = d_sumsq[tid]*inv - mu*mu;
                float a = gamma[tid]*rsqrtf(var + 1e-5f);
                d_bna[tid] = a;
                d_bnb[tid] = beta[tid] - mu*a;
            }
            if (tid == 0) d_bnctr = 0;
        }
    } else if (bx < nbbn + npz){
        int n0 = (bx - nbbn)*1000;
        int npb = N / NB;
        int b = n0 / npb;
        int k = tid & 31, slot = tid >> 5;
        float z = 0.f;
        for (int i = slot; i < 1000; i += 8)
            z += __expf(probs[(n0+i)*KP + k]);
        __shared__ float sr[8][KP];
        sr[slot][k] = z;
        __syncthreads();
        if (tid < KP){
            float zz = sr[0][tid];
            #pragma unroll
            for (int s2 = 1; s2 < 8; s2++) zz += sr[s2][tid];
            atomicAdd(&d_pz[b*KP + tid], zz);
        }
    } else {
        int n = (bx - nbbn - npz)*256 + tid;
        if (n < N){
            int b = coords[4*n], x = coords[4*n+1], y = coords[4*n+2], z = coords[4*n+3];
            d_grid[b*GRID3 + (x<<14) + (y<<7) + z] = 0;
        }
    }
}

// ---------------- ctx: 10-point rounds ----------------
__global__ void __launch_bounds__(256)
k_ctx(const int* __restrict__ coords, const float* __restrict__ probs, int N){
    __shared__ float wsh[2][10][KP];
    __shared__ float szs[KP];
    int n0 = blockIdx.x*200;
    if (n0 >= N) return;
    int b = coords[4*n0];
    int tid = threadIdx.x;
    int half = tid >> 7, t = tid & 127;
    if (tid < KP) szs[tid] = d_pz[b*KP + tid];
    float ba = d_bna[t], bb = d_bnb[t];
    __syncthreads();
    float acc[KP];
    #pragma unroll
    for (int k = 0; k < KP; k++) acc[k] = 0.f;
    int base = n0 + half*100;
    for (int g = 0; g < 100; g += 10){
        {
            int p = t >> 5, k = t & 31;
            int n = base + g + p;
            wsh[half][p][k] = (n < N) ? __expf(probs[n*KP + k]) / szs[k] : 0.f;
        }
        {
            int p = 4 + (t >> 5), k = t & 31;
            int n = base + g + p;
            wsh[half][p][k] = (n < N) ? __expf(probs[n*KP + k]) / szs[k] : 0.f;
        }
        if (t < 64){
            int p = 8 + (t >> 5), k = t & 31;
            int n = base + g + p;
            wsh[half][p][k] = (n < N) ? __expf(probs[n*KP + k]) / szs[k] : 0.f;
        }
        __syncthreads();
        #pragma unroll
        for (int p2 = 0; p2 < 10; p2++){
            int n2 = base + g + p2;
            float xv = (n2 < N) ? fmaxf(fmaf(d_x[n2*CH + t], ba, bb), 0.f) : 0.f;
            #pragma unroll
            for (int k2 = 0; k2 < KP; k2++) acc[k2] += wsh[half][p2][k2]*xv;
        }
        __syncthreads();
    }
    #pragma unroll
    for (int k2 = 0; k2 < KP; k2++)
        atomicAdd(&d_ctx[(b*KP+k2)*CH + t], acc[k2]);
}

// ---------------- K/V projections ----------------
__global__ void k_kvproj(const float* __restrict__ ipb){
    int row = blockIdx.x;
    int co = threadIdx.x;
    __shared__ float cr[CH];
    cr[co] = d_ctx[row*CH + co];
    __syncthreads();
    float ak = 0.f, av = 0.f;
    #pragma unroll 8
    for (int ci = 0; ci < CH; ci++){
        float c = cr[ci];
        ak += c*d_WT[CH*CH   + ci*CH + co];
        av += c*d_WT[2*CH*CH + ci*CH + co];
    }
    d_kh[row*CH + co] = ak + ipb[CH + co];
    d_vh[row*CH + co] = av + ipb[2*CH + co];
}

// ======== fused q-GEMM + attention + output GEMM (512 threads, 16 warps) ========
#define FQ_R1 0
#define FQ_R2 69632
#define FQ_KV 139264
#define FQ_TOT 172032

__global__ void __launch_bounds__(512, 1)
k_attn_out(const int* __restrict__ coords, const float* __restrict__ ipb,
           float* __restrict__ out, int N){
    extern __shared__ char sm[];
    unsigned sb = smem_u32(sm);
    __nv_bfloat16* r1h = (__nv_bfloat16*)(sm + FQ_R1);
    __nv_bfloat16* r1l = r1h + 128*SA;
    __nv_bfloat16* r2h = (__nv_bfloat16*)(sm + FQ_R2);
    __nv_bfloat16* r2l = r2h + 128*SA;
    float* qsm = (float*)(sm + FQ_R1);
    float* sK = (float*)(sm + FQ_KV);
    float* sV = sK + KP*CH;
    int tid = threadIdx.x;
    int wid = tid >> 5, lane = tid & 31;
    int n0 = blockIdx.x*128;
    if (n0 >= N) return;
    int b0 = coords[4*n0];
    int b1 = coords[4*min(n0 + 127, N - 1)];

    // staging: x tile (BN+ReLU) -> R1; Wq -> R2; K/V -> R3
    {
        int r = tid >> 2, c0 = (tid & 3)*32;
        int g = n0 + r;
        #pragma unroll
        for (int cc = 0; cc < 32; cc += 4){
            int c = c0 + cc;
            float4 v = make_float4(0.f,0.f,0.f,0.f);
            if (g < N) v = *(const float4*)&d_x[g*CH + c];
            v.x = fmaxf(fmaf(v.x, d_bna[c  ], d_bnb[c  ]), 0.f);
            v.y = fmaxf(fmaf(v.y, d_bna[c+1], d_bnb[c+1]), 0.f);
            v.z = fmaxf(fmaf(v.z, d_bna[c+2], d_bnb[c+2]), 0.f);
            v.w = fmaxf(fmaf(v.w, d_bna[c+3], d_bnb[c+3]), 0.f);
            split_store(r1h, r1l, r*SA + c, v);
        }
    }
    {
        const int4* src = (const int4*)(d_Wb + 2*CH*CH);
        #pragma unroll
        for (int i = tid; i < 4096; i += 512){
            int sel = i >> 11, rem = i & 2047;
            int r = rem >> 4, c8 = rem & 15;
            __nv_bfloat16* dst = (sel ? r2l : r2h) + r*SA + c8*8;
            *(int4*)dst = src[i];
        }
    }
    for (int i = tid; i < KP*CH/4; i += 512){
        ((float4*)sK)[i] = ((const float4*)(d_kh + b0*KP*CH))[i];
        ((float4*)sV)[i] = ((const float4*)(d_vh + b0*KP*CH))[i];
    }
    __syncthreads();

    // Phase 1: q = 0.25*(x' @ Wq.T + bq), 16 warps
    {
        float qacc[2][4][4];
        mma_main_16w(sb + FQ_R1, sb + FQ_R1 + 128*SA*2, sb + FQ_R2, sb + FQ_R2 + 128*SA*2,
                     wid, lane, qacc);
        __syncthreads();   // all reads of R1/R2 done
        int mrow = (wid & 3)*32, ncol = (wid >> 2)*32;
        int rbase = mrow + (lane >> 2);
        int cbase = ncol + 2*(lane & 3);
        #pragma unroll
        for (int ni = 0; ni < 4; ni++){
            int col = cbase + ni*8;
            float b0f = ipb[col], b1f = ipb[col+1];
            #pragma unroll
            for (int mi = 0; mi < 2; mi++){
                int r0 = rbase + mi*16;
                *(float2*)&qsm[r0*132 + col] =
                    make_float2(0.25f*(qacc[mi][ni][0]+b0f), 0.25f*(qacc[mi][ni][1]+b1f));
                *(float2*)&qsm[(r0+8)*132 + col] =
                    make_float2(0.25f*(qacc[mi][ni][2]+b0f), 0.25f*(qacc[mi][ni][3]+b1f));
            }
        }
    }
    __syncthreads();

    // Phase 2: attention; 16 warps x 8 points; o -> R2
    for (int pp = 0; pp < 8; pp += 2){
        int r1 = wid*8 + pp;
        int n1 = n0 + r1, n2 = n1 + 1;
        bool one = (n1 < N), two = (n2 < N);
        int bsel = (one && coords[4*n1] != b0) ? 1 : 0;
        float4 q1 = *(const float4*)&qsm[r1*132 + 4*lane];
        float4 q2 = *(const float4*)&qsm[(r1+1)*132 + 4*lane];
        float s1[KP], s2[KP];
        #pragma unroll
        for (int k = 0; k < KP; k++){
            float4 kv = bsel ? *(const float4*)&d_kh[(b1*KP + k)*CH + 4*lane]
                             : *(const float4*)&sK[k*CH + 4*lane];
            s1[k] = q1.x*kv.x + q1.y*kv.y + q1.z*kv.z + q1.w*kv.w;
            s2[k] = q2.x*kv.x + q2.y*kv.y + q2.z*kv.z + q2.w*kv.w;
        }
        #pragma unroll
        for (int k = 0; k < KP; k++){
            s1[k] += __shfl_xor_sync(0xffffffffu, s1[k], 1);
            s1[k] += __shfl_xor_sync(0xffffffffu, s1[k], 2);
            s2[k] += __shfl_xor_sync(0xffffffffu, s2[k], 1);
            s2[k] += __shfl_xor_sync(0xffffffffu, s2[k], 2);
        }
        float m1 = -3.4e38f, m2 = -3.4e38f;
        #pragma unroll
        for (int k = 0; k < KP; k++){ m1 = fmaxf(m1, s1[k]); m2 = fmaxf(m2, s2[k]); }
        float z1 = 0.f, z2 = 0.f;
        #pragma unroll
        for (int k = 0; k < KP; k++){
            s1[k] = __expf(s1[k] - m1); z1 += s1[k];
            s2[k] = __expf(s2[k] - m2); z2 += s2[k];
        }
        float i1 = 1.f/z1, i2 = 1.f/z2;
        float4 o1 = make_float4(0,0,0,0), o2 = make_float4(0,0,0,0);
        #pragma unroll
        for (int k = 0; k < KP; k++){
            float4 vvv = bsel ? *(const float4*)&d_vh[(b1*KP + k)*CH + 4*lane]
                              : *(const float4*)&sV[k*CH + 4*lane];
            o1.x += s1[k]*vvv.x; o1.y += s1[k]*vvv.y; o1.z += s1[k]*vvv.z; o1.w += s1[k]*vvv.w;
            o2.x += s2[k]*vvv.x; o2.y += s2[k]*vvv.y; o2.z += s2[k]*vvv.z; o2.w += s2[k]*vvv.w;
        }
        if (!one){ o1 = make_float4(0,0,0,0); i1 = 0.f; }
        if (!two){ o2 = make_float4(0,0,0,0); i2 = 0.f; }
        o1.x*=i1; o1.y*=i1; o1.z*=i1; o1.w*=i1;
        o2.x*=i2; o2.y*=i2; o2.z*=i2; o2.w*=i2;
        split_store(r2h, r2l, r1*SA + 4*lane, o1);
        split_store(r2h, r2l, (r1+1)*SA + 4*lane, o2);
    }
    __syncthreads();   // attention done (q reads finished)

    // Phase 3: W2 -> R1, then out = o @ W2.T + b2
    {
        const int4* src = (const int4*)(d_Wb + 4*CH*CH);
        #pragma unroll
        for (int i = tid; i < 4096; i += 512){
            int sel = i >> 11, rem = i & 2047;
            int r = rem >> 4, c8 = rem & 15;
            __nv_bfloat16* dst = (sel ? r1l : r1h) + r*SA + c8*8;
            *(int4*)dst = src[i];
        }
    }
    __syncthreads();
    {
        float acc[2][4][4];
        mma_main_16w(sb + FQ_R2, sb + FQ_R2 + 128*SA*2, sb + FQ_R1, sb + FQ_R1 + 128*SA*2,
                     wid, lane, acc);
        int mrow = (wid & 3)*32, ncol = (wid >> 2)*32;
        int rbase = n0 + mrow + (lane >> 2);
        int cbase = ncol + 2*(lane & 3);
        #pragma unroll
        for (int ni = 0; ni < 4; ni++){
            int col = cbase + ni*8;
            float b0f = d_b2[col], b1f = d_b2[col+1];
            #pragma unroll
            for (int mi = 0; mi < 2; mi++){
                int g0 = rbase + mi*16;
                if (g0 < N)
                    *(float2*)&out[g0*CH + col] =
                        make_float2(acc[mi][ni][0]+b0f, acc[mi][ni][1]+b1f);
                if (g0 + 8 < N)
                    *(float2*)&out[(g0+8)*CH + col] =
                        make_float2(acc[mi][ni][2]+b0f, acc[mi][ni][3]+b1f);
            }
        }
    }
}

extern "C" void kernel_launch(void* const* d_in, const int* in_sizes, int n_in,
                              void* d_out, int out_size){
    const float* feats  = (const float*)d_in[0];
    const float* probs  = (const float*)d_in[1];
    const float* conv_w = (const float*)d_in[2];
    const float* gamma  = (const float*)d_in[3];
    const float* beta   = (const float*)d_in[4];
    const float* ipw    = (const float*)d_in[5];
    const float* ipb    = (const float*)d_in[6];
    const float* opw    = (const float*)d_in[7];
    const float* opb    = (const float*)d_in[8];
    const float* bw     = (const float*)d_in[9];
    const int*   coords = (const int*)d_in[10];
    float* out = (float*)d_out;
    int N = in_sizes[0] / CH;

    static float* dx_p=nullptr;
    static __nv_bfloat16* dwb_p=nullptr;
    if (!dx_p){
        cudaGetSymbolAddress((void**)&dx_p,  d_x);
        cudaGetSymbolAddress((void**)&dwb_p, d_Wb);
        cudaFuncSetAttribute(k_gemm_mma,    cudaFuncAttributeMaxDynamicSharedMemorySize, G64_SMEM);
        cudaFuncSetAttribute(k_attn_out,    cudaFuncAttributeMaxDynamicSharedMemorySize, FQ_TOT);
        cudaFuncSetAttribute(k_conv_sparse, cudaFuncAttributeMaxDynamicSharedMemorySize, G64_SMEM);
    }
    int nb256 = (N + 255)/256;
    int nbA = (N + 127)/128;
    int ntile = (N + 63)/64;
    int gG = min(296, ntile);
    int npz = N/1000;

    k_prep<<<401, 256>>>(ipw, conv_w, bw, opw, opb);
    k_build_grid<<<nb256, 256>>>(coords, N);
    k_build_pairs<<<nb256, 256>>>(coords, N);
    k_gemm_mma<<<gG, 256, G64_SMEM>>>(feats, dwb_p, dx_p, N);
    k_conv_sparse<<<dim3(8, 26), 256, G64_SMEM>>>(feats);
    k_mid<<<nb256 + npz + nb256, 256>>>(gamma, beta, probs, coords, N, nb256, npz);
    k_ctx<<<(N+199)/200, 256>>>(coords, probs, N);
    k_kvproj<<<NB*KP, 128>>>(ipb);
    k_attn_out<<<nbA, 512, FQ_TOT>>>(coords, ipb, out, N);
}